// round 1
// baseline (speedup 1.0000x reference)
#include <cuda_runtime.h>
#include <math.h>

#define NNODES 50000
#define NEDGES 200000
#define TOTE   (NEDGES + NNODES)
#define EMB    300
#define EMB4   75          // EMB / 4 (float4 chunks)
#define DK     256
#define BGR    1000
#define NPER   50
#define NLAYERS 5
#define PADF   16

// ---------------- scratch (device globals; no allocation allowed) ----------------
__device__ float g_h[NNODES * EMB];     // current node features
__device__ float g_hW[NNODES * EMB];    // h @ W.T + b
__device__ float g_hnew[NNODES * EMB];  // scatter accumulator
__device__ float g_mf[BGR * EMB];
__device__ float g_ve[2 * EMB];         // ew1[l] @ W.T
__device__ float g_Q[BGR * DK];
__device__ float g_qk[BGR * EMB];
__device__ float g_wsum[BGR * EMB];
__device__ float g_mean[BGR * EMB];
__device__ float g_wqt[EMB * DK];
__device__ float g_wvt[EMB * DK];
__device__ float g_mlt[EMB * DK];
__device__ float g_lgt[EMB * DK];
__device__ float g_ph1t[DK * 512];

// ---------------- node init: h = x_emb[x_type] + x_feat @ x_weight; hnew = 0 -----
__global__ void k_init(const int* __restrict__ x_type, const float* __restrict__ x_feat,
                       const float* __restrict__ x_emb, const float* __restrict__ x_weight)
{
    int idx = blockIdx.x * blockDim.x + threadIdx.x;
    if (idx >= NNODES * EMB4) return;
    int n = idx / EMB4, c = idx % EMB4;
    int t = __ldg(x_type + n);
    float4 acc = __ldg((const float4*)(x_emb + (size_t)t * EMB) + c);
#pragma unroll
    for (int k = 0; k < PADF; k++) {
        float f = __ldg(x_feat + (size_t)n * PADF + k);
        float4 w = __ldg((const float4*)(x_weight + (size_t)k * EMB) + c);
        acc.x = fmaf(f, w.x, acc.x); acc.y = fmaf(f, w.y, acc.y);
        acc.z = fmaf(f, w.z, acc.z); acc.w = fmaf(f, w.w, acc.w);
    }
    ((float4*)g_h)[idx] = acc;
    ((float4*)g_hnew)[idx] = make_float4(0.f, 0.f, 0.f, 0.f);
}

// ---------------- metal feature: mf = metal_feat @ me1_w.T + me1_b + me2[type] ---
__global__ void k_mf(const int* __restrict__ metal_type, const float* __restrict__ metal_feat,
                     const float* __restrict__ me1_w, const float* __restrict__ me1_b,
                     const float* __restrict__ me2)
{
    int idx = blockIdx.x * blockDim.x + threadIdx.x;
    if (idx >= BGR * EMB) return;
    int b = idx / EMB, j = idx % EMB;
    float acc = __ldg(me1_b + j) + __ldg(me2 + (size_t)__ldg(metal_type + b) * EMB + j);
#pragma unroll
    for (int k = 0; k < 17; k++)
        acc = fmaf(__ldg(metal_feat + (size_t)b * 17 + k), __ldg(me1_w + (size_t)j * 17 + k), acc);
    g_mf[idx] = acc;
}

// ---------------- transpose readout weights once -------------------------------
__global__ void k_transpose_all(const float* __restrict__ wq, const float* __restrict__ wv,
                                const float* __restrict__ ml, const float* __restrict__ lg,
                                const float* __restrict__ ph1)
{
    int idx = blockIdx.x * blockDim.x + threadIdx.x;
    const int SZ1 = DK * EMB;                 // 76800
    if (idx < 4 * SZ1) {
        int w = idx / SZ1, i = idx % SZ1;
        int d = i / EMB, j = i % EMB;
        float v = (w == 0) ? wq[i] : (w == 1) ? wv[i] : (w == 2) ? ml[i] : lg[i];
        float* dst = (w == 0) ? g_wqt : (w == 1) ? g_wvt : (w == 2) ? g_mlt : g_lgt;
        dst[(size_t)j * DK + d] = v;
    } else {
        int i = idx - 4 * SZ1;
        if (i < 512 * DK) {
            int o = i / DK, d = i % DK;
            g_ph1t[(size_t)d * 512 + o] = ph1[i];
        }
    }
}

// ---------------- per-layer edge vectors: ve[w][j] = sum_k ew[w,k] * W[j,k] -----
__global__ void k_ve(const float* __restrict__ ew, const float* __restrict__ W)
{
    int j = blockIdx.x * blockDim.x + threadIdx.x;
    if (j >= 2 * EMB) return;
    int which = j / EMB, col = j % EMB;
    const float* e = ew + which * EMB;
    const float* wr = W + (size_t)col * EMB;
    float acc = 0.f;
    for (int k = 0; k < EMB; k++) acc = fmaf(__ldg(e + k), __ldg(wr + k), acc);
    g_ve[j] = acc;
}

// ---------------- GEMM: hW[m,j] = sum_k h[m,k] * W[j,k] + bias[j] ---------------
#define GBM 128
#define GBJ 64
#define GBK 16
__global__ void __launch_bounds__(256) k_gemm(const float* __restrict__ W,
                                              const float* __restrict__ bias)
{
    __shared__ float As[GBK][GBM];
    __shared__ float Bs[GBK][GBJ];
    int m0 = blockIdx.x * GBM;
    int j0 = blockIdx.y * GBJ;
    int tid = threadIdx.x;
    int tx = tid & 15, ty = tid >> 4;
    float acc[8][4];
#pragma unroll
    for (int r = 0; r < 8; r++)
#pragma unroll
        for (int c = 0; c < 4; c++) acc[r][c] = 0.f;

    for (int k0 = 0; k0 < EMB; k0 += GBK) {
        // A tile: 128 x 16 (512 float4, 2 per thread), store transposed
#pragma unroll
        for (int it = 0; it < 2; it++) {
            int li = tid * 2 + it;
            int mm = li >> 2, cc = li & 3;
            int m = m0 + mm, kk = k0 + cc * 4;
            float4 v = make_float4(0.f, 0.f, 0.f, 0.f);
            if (m < NNODES && kk + 3 < EMB)
                v = *(const float4*)(g_h + (size_t)m * EMB + kk);
            As[cc * 4 + 0][mm] = v.x; As[cc * 4 + 1][mm] = v.y;
            As[cc * 4 + 2][mm] = v.z; As[cc * 4 + 3][mm] = v.w;
        }
        // B tile: 64 x 16 (256 float4, 1 per thread), store transposed
        {
            int jj = tid >> 2, cc = tid & 3;
            int j = j0 + jj, kk = k0 + cc * 4;
            float4 v = make_float4(0.f, 0.f, 0.f, 0.f);
            if (j < EMB && kk + 3 < EMB)
                v = *(const float4*)(W + (size_t)j * EMB + kk);
            Bs[cc * 4 + 0][jj] = v.x; Bs[cc * 4 + 1][jj] = v.y;
            Bs[cc * 4 + 2][jj] = v.z; Bs[cc * 4 + 3][jj] = v.w;
        }
        __syncthreads();
#pragma unroll
        for (int k = 0; k < GBK; k++) {
            float4 b4 = *(const float4*)&Bs[k][tx * 4];
            float4 a0 = *(const float4*)&As[k][ty * 8];
            float4 a1 = *(const float4*)&As[k][ty * 8 + 4];
            float av[8] = {a0.x, a0.y, a0.z, a0.w, a1.x, a1.y, a1.z, a1.w};
            float bv[4] = {b4.x, b4.y, b4.z, b4.w};
#pragma unroll
            for (int r = 0; r < 8; r++)
#pragma unroll
                for (int c = 0; c < 4; c++) acc[r][c] = fmaf(av[r], bv[c], acc[r][c]);
        }
        __syncthreads();
    }
    int j = j0 + tx * 4;
    if (j + 3 < EMB) {
        float4 bb = *(const float4*)(bias + j);
#pragma unroll
        for (int r = 0; r < 8; r++) {
            int m = m0 + ty * 8 + r;
            if (m < NNODES) {
                float4 o;
                o.x = acc[r][0] + bb.x; o.y = acc[r][1] + bb.y;
                o.z = acc[r][2] + bb.z; o.w = acc[r][3] + bb.w;
                *(float4*)(g_hW + (size_t)m * EMB + j) = o;
            }
        }
    }
}

// ---------------- scatter: hnew[col] += relu(hW[row] + a0*ve0 + a1*ve1) ---------
__global__ void k_scatter(const int* __restrict__ eidx, const float* __restrict__ eattr)
{
    int gw = (blockIdx.x * blockDim.x + threadIdx.x) >> 5;
    if (gw >= TOTE) return;
    int lane = threadIdx.x & 31;
    int r, cn; float a0, a1;
    if (gw < NEDGES) {
        r  = __ldg(eidx + gw);
        cn = __ldg(eidx + NEDGES + gw);
        float2 ea = __ldg((const float2*)eattr + gw);
        a0 = ea.x; a1 = ea.y;
    } else {
        r = cn = gw - NEDGES; a0 = 0.f; a1 = 4.f;  // self-loop, attr (0,4)
    }
    const float4* src = (const float4*)(g_hW + (size_t)r * EMB);
    float4* dst = (float4*)(g_hnew + (size_t)cn * EMB);
#pragma unroll
    for (int i = 0; i < 3; i++) {
        int c = lane + 32 * i;
        if (c < EMB4) {
            float4 x  = src[c];
            float4 e0 = __ldg((const float4*)g_ve + c);
            float4 e1 = __ldg((const float4*)g_ve + EMB4 + c);
            float4 m;
            m.x = fmaxf(fmaf(a1, e1.x, fmaf(a0, e0.x, x.x)), 0.f);
            m.y = fmaxf(fmaf(a1, e1.y, fmaf(a0, e0.y, x.y)), 0.f);
            m.z = fmaxf(fmaf(a1, e1.z, fmaf(a0, e0.z, x.z)), 0.f);
            m.w = fmaxf(fmaf(a1, e1.w, fmaf(a0, e0.w, x.w)), 0.f);
            atomicAdd(dst + c, m);   // 128-bit vector atomic (sm_90+)
        }
    }
}

// ---------------- batchnorm (+relu) hnew -> h, and zero hnew for next layer -----
__global__ void k_bn(const float* __restrict__ rm, const float* __restrict__ rv,
                     const float* __restrict__ gg, const float* __restrict__ bb,
                     int do_relu)
{
    int idx = blockIdx.x * blockDim.x + threadIdx.x;
    if (idx >= NNODES * EMB4) return;
    int c = idx % EMB4;
    float4 x = ((const float4*)g_hnew)[idx];
    float4 m = __ldg((const float4*)rm + c);
    float4 v = __ldg((const float4*)rv + c);
    float4 g4 = __ldg((const float4*)gg + c);
    float4 b4 = __ldg((const float4*)bb + c);
    float4 y;
    y.x = (x.x - m.x) * rsqrtf(v.x + 1e-5f) * g4.x + b4.x;
    y.y = (x.y - m.y) * rsqrtf(v.y + 1e-5f) * g4.y + b4.y;
    y.z = (x.z - m.z) * rsqrtf(v.z + 1e-5f) * g4.z + b4.z;
    y.w = (x.w - m.w) * rsqrtf(v.w + 1e-5f) * g4.w + b4.w;
    if (do_relu) {
        y.x = fmaxf(y.x, 0.f); y.y = fmaxf(y.y, 0.f);
        y.z = fmaxf(y.z, 0.f); y.w = fmaxf(y.w, 0.f);
    }
    ((float4*)g_h)[idx] = y;
    ((float4*)g_hnew)[idx] = make_float4(0.f, 0.f, 0.f, 0.f);
}

// ---------------- readout: Q = mf @ wq.T (via transposed weights) ---------------
__global__ void k_q()
{
    __shared__ float mfs[4][EMB];
    int b0 = blockIdx.x * 4, tid = threadIdx.x;
    for (int i = tid; i < 4 * EMB; i += 256)
        mfs[i / EMB][i % EMB] = g_mf[(size_t)(b0 + i / EMB) * EMB + i % EMB];
    __syncthreads();
    float acc[4] = {0.f, 0.f, 0.f, 0.f};
    for (int j = 0; j < EMB; j++) {
        float w = g_wqt[(size_t)j * DK + tid];
#pragma unroll
        for (int g = 0; g < 4; g++) acc[g] = fmaf(mfs[g][j], w, acc[g]);
    }
#pragma unroll
    for (int g = 0; g < 4; g++) g_Q[(size_t)(b0 + g) * DK + tid] = acc[g];
}

// ---------------- qk[b,i] = sum_d Q[b,d] * wk[d,i] ------------------------------
__global__ void k_qk(const float* __restrict__ wk)
{
    __shared__ float Qs[4][DK];
    int b0 = blockIdx.x * 4, tid = threadIdx.x;   // 320 threads
    for (int i = tid; i < 4 * DK; i += 320)
        Qs[i / DK][i % DK] = g_Q[(size_t)(b0 + i / DK) * DK + i % DK];
    __syncthreads();
    if (tid < EMB) {
        float acc[4] = {0.f, 0.f, 0.f, 0.f};
        for (int d = 0; d < DK; d++) {
            float w = __ldg(wk + (size_t)d * EMB + tid);
#pragma unroll
            for (int g = 0; g < 4; g++) acc[g] = fmaf(Qs[g][d], w, acc[g]);
        }
#pragma unroll
        for (int g = 0; g < 4; g++) g_qk[(size_t)(b0 + g) * EMB + tid] = acc[g];
    }
}

// ---------------- per-graph attention: wsum = softmax(qk.h/16) @ h, mean --------
__global__ void k_attn()
{
    __shared__ float qks[EMB];
    __shared__ float sc[NPER];
    __shared__ float p[NPER];
    int b = blockIdx.x, tid = threadIdx.x;
    for (int i = tid; i < EMB; i += 256) qks[i] = g_qk[(size_t)b * EMB + i];
    __syncthreads();
    int warp = tid >> 5, lane = tid & 31;
    const float* hb = g_h + (size_t)b * NPER * EMB;
    for (int k = warp; k < NPER; k += 8) {
        float s = 0.f;
        for (int i = lane; i < EMB; i += 32) s = fmaf(qks[i], hb[(size_t)k * EMB + i], s);
#pragma unroll
        for (int off = 16; off; off >>= 1) s += __shfl_xor_sync(0xffffffffu, s, off);
        if (lane == 0) sc[k] = s * (1.0f / 16.0f);
    }
    __syncthreads();
    if (tid == 0) {
        float mx = -1e30f;
        for (int k = 0; k < NPER; k++) mx = fmaxf(mx, sc[k]);
        float ssum = 0.f;
        for (int k = 0; k < NPER; k++) { float e = expf(sc[k] - mx); p[k] = e; ssum += e; }
        float inv = 1.f / ssum;
        for (int k = 0; k < NPER; k++) p[k] *= inv;
    }
    __syncthreads();
    for (int j = tid; j < EMB; j += 256) {
        float ws = 0.f, mn = 0.f;
        for (int k = 0; k < NPER; k++) {
            float v = hb[(size_t)k * EMB + j];
            ws = fmaf(p[k], v, ws); mn += v;
        }
        g_wsum[(size_t)b * EMB + j] = ws;
        g_mean[(size_t)b * EMB + j] = mn * (1.0f / NPER);
    }
}

// ---------------- final head ----------------------------------------------------
__global__ void k_final(const float* __restrict__ ml_b, const float* __restrict__ lg_b,
                        const float* __restrict__ ph1_b, const float* __restrict__ ph2_w,
                        const float* __restrict__ ph2_b, float* __restrict__ out)
{
    __shared__ float ws[4][EMB], mfs[4][EMB], mns[4][EMB];
    __shared__ float feat[4][DK];
    __shared__ float red[256];
    int b0 = blockIdx.x * 4, tid = threadIdx.x;
    for (int i = tid; i < 4 * EMB; i += 256) {
        int g = i / EMB, j = i % EMB;
        ws[g][j]  = g_wsum[(size_t)(b0 + g) * EMB + j];
        mfs[g][j] = g_mf[(size_t)(b0 + g) * EMB + j];
        mns[g][j] = g_mean[(size_t)(b0 + g) * EMB + j];
    }
    __syncthreads();
    int d = tid;
    float a[4], m2[4], lg[4];
    float mb = __ldg(ml_b + d), lb = __ldg(lg_b + d);
#pragma unroll
    for (int g = 0; g < 4; g++) { a[g] = 0.f; m2[g] = mb; lg[g] = lb; }
    for (int k = 0; k < EMB; k++) {
        float wv_ = g_wvt[(size_t)k * DK + d];
        float ml_ = g_mlt[(size_t)k * DK + d];
        float lg_ = g_lgt[(size_t)k * DK + d];
#pragma unroll
        for (int g = 0; g < 4; g++) {
            a[g]  = fmaf(wv_, ws[g][k],  a[g]);
            m2[g] = fmaf(ml_, mfs[g][k], m2[g]);
            lg[g] = fmaf(lg_, mns[g][k], lg[g]);
        }
    }
#pragma unroll
    for (int g = 0; g < 4; g++)
        feat[g][d] = fmaxf(a[g], 0.f) + fmaxf(m2[g], 0.f) + fmaxf(lg[g], 0.f);
    __syncthreads();
    float part[4] = {0.f, 0.f, 0.f, 0.f};
#pragma unroll
    for (int rep = 0; rep < 2; rep++) {
        int o = tid + rep * 256;
        float t[4];
        float pb = __ldg(ph1_b + o);
#pragma unroll
        for (int g = 0; g < 4; g++) t[g] = pb;
        for (int k = 0; k < DK; k++) {
            float w = g_ph1t[(size_t)k * 512 + o];
#pragma unroll
            for (int g = 0; g < 4; g++) t[g] = fmaf(w, feat[g][k], t[g]);
        }
        float p2 = __ldg(ph2_w + o);
#pragma unroll
        for (int g = 0; g < 4; g++) {
            float x = t[g];
            float sp = (x > 20.f) ? x : log1pf(expf(x));
            part[g] = fmaf(sp, p2, part[g]);
        }
    }
    for (int g = 0; g < 4; g++) {
        red[tid] = part[g];
        __syncthreads();
        for (int s = 128; s; s >>= 1) {
            if (tid < s) red[tid] += red[tid + s];
            __syncthreads();
        }
        if (tid == 0) out[b0 + g] = red[0] + __ldg(ph2_b);
        __syncthreads();
    }
}

// ---------------- launch --------------------------------------------------------
extern "C" void kernel_launch(void* const* d_in, const int* in_sizes, int n_in,
                              void* d_out, int out_size)
{
    const int*   x_type     = (const int*)d_in[0];
    const float* x_feat     = (const float*)d_in[1];
    const int*   edge_index = (const int*)d_in[2];
    const float* edge_attr  = (const float*)d_in[3];
    const int*   metal_type = (const int*)d_in[4];
    const float* metal_feat = (const float*)d_in[5];
    const float* x_emb      = (const float*)d_in[6];
    const float* x_weight   = (const float*)d_in[7];
    const float* ew1        = (const float*)d_in[8];
    const float* mlp_w      = (const float*)d_in[9];
    const float* mlp_b      = (const float*)d_in[10];
    const float* bn_g       = (const float*)d_in[11];
    const float* bn_b       = (const float*)d_in[12];
    const float* bn_rm      = (const float*)d_in[13];
    const float* bn_rv      = (const float*)d_in[14];
    const float* me1_w      = (const float*)d_in[15];
    const float* me1_b      = (const float*)d_in[16];
    const float* me2        = (const float*)d_in[17];
    const float* wq         = (const float*)d_in[18];
    const float* wk         = (const float*)d_in[19];
    const float* wv         = (const float*)d_in[20];
    const float* ml_w       = (const float*)d_in[21];
    const float* ml_b       = (const float*)d_in[22];
    const float* lg_w       = (const float*)d_in[23];
    const float* lg_b       = (const float*)d_in[24];
    const float* ph1_w      = (const float*)d_in[25];
    const float* ph1_b      = (const float*)d_in[26];
    const float* ph2_w      = (const float*)d_in[27];
    const float* ph2_b      = (const float*)d_in[28];
    float* out = (float*)d_out;

    k_init<<<(NNODES * EMB4 + 255) / 256, 256>>>(x_type, x_feat, x_emb, x_weight);
    k_mf<<<(BGR * EMB + 255) / 256, 256>>>(metal_type, metal_feat, me1_w, me1_b, me2);
    k_transpose_all<<<(4 * DK * EMB + 512 * DK + 255) / 256, 256>>>(wq, wv, ml_w, lg_w, ph1_w);

    for (int l = 0; l < NLAYERS; l++) {
        const float* Wl = mlp_w + (size_t)l * EMB * EMB;
        k_ve<<<3, 256>>>(ew1 + (size_t)l * 2 * EMB, Wl);
        dim3 gg((NNODES + GBM - 1) / GBM, (EMB + GBJ - 1) / GBJ);
        k_gemm<<<gg, 256>>>(Wl, mlp_b + (size_t)l * EMB);
        k_scatter<<<(TOTE * 32 + 255) / 256, 256>>>(edge_index, edge_attr);
        k_bn<<<(NNODES * EMB4 + 255) / 256, 256>>>(bn_rm + (size_t)l * EMB, bn_rv + (size_t)l * EMB,
                                                   bn_g + (size_t)l * EMB, bn_b + (size_t)l * EMB,
                                                   l < NLAYERS - 1 ? 1 : 0);
    }

    k_q<<<BGR / 4, 256>>>();
    k_qk<<<BGR / 4, 320>>>(wk);
    k_attn<<<BGR, 256>>>();
    k_final<<<BGR / 4, 256>>>(ml_b, lg_b, ph1_b, ph2_w, ph2_b, out);
}

// round 3
// speedup vs baseline: 1.3517x; 1.3517x over previous
#include <cuda_runtime.h>
#include <cuda_bf16.h>
#include <math.h>
#include <stdint.h>

#define NNODES 50000
#define NEDGES 200000
#define TOTE   (NEDGES + NNODES)
#define EMB    300
#define EMB4   75
#define DK     256
#define BGR    1000
#define NPER   50
#define NLAYERS 5
#define PADF   16

// ---------------- scratch (device globals) ----------------
__device__ float g_h[NNODES * EMB];
__device__ float g_hW[NNODES * EMB];
__device__ float g_mf[BGR * EMB];
__device__ float g_ve_all[NLAYERS * 2 * EMB];
__device__ float g_Q[BGR * DK];
__device__ float g_qk[BGR * EMB];
__device__ float g_wsum[BGR * EMB];
__device__ float g_mean[BGR * EMB];
__device__ float g_wqt[EMB * DK];
__device__ float g_wvt[EMB * DK];
__device__ float g_mlt[EMB * DK];
__device__ float g_lgt[EMB * DK];
__device__ float g_ph1t[DK * 512];
// CSR
__device__ int g_deg[NNODES];
__device__ int g_off[NNODES + 1];
__device__ int g_cur[NNODES];
__device__ int g_csr_src[TOTE];
__device__ float2 g_csr_ea[TOTE];

// ---------------- node init ----------------
__global__ void k_init(const int* __restrict__ x_type, const float* __restrict__ x_feat,
                       const float* __restrict__ x_emb, const float* __restrict__ x_weight)
{
    int idx = blockIdx.x * blockDim.x + threadIdx.x;
    if (idx >= NNODES * EMB4) return;
    int n = idx / EMB4, c = idx % EMB4;
    int t = __ldg(x_type + n);
    float4 acc = __ldg((const float4*)(x_emb + (size_t)t * EMB) + c);
#pragma unroll
    for (int k = 0; k < PADF; k++) {
        float f = __ldg(x_feat + (size_t)n * PADF + k);
        float4 w = __ldg((const float4*)(x_weight + (size_t)k * EMB) + c);
        acc.x = fmaf(f, w.x, acc.x); acc.y = fmaf(f, w.y, acc.y);
        acc.z = fmaf(f, w.z, acc.z); acc.w = fmaf(f, w.w, acc.w);
    }
    ((float4*)g_h)[idx] = acc;
}

// ---------------- metal feature ----------------
__global__ void k_mf(const int* __restrict__ metal_type, const float* __restrict__ metal_feat,
                     const float* __restrict__ me1_w, const float* __restrict__ me1_b,
                     const float* __restrict__ me2)
{
    int idx = blockIdx.x * blockDim.x + threadIdx.x;
    if (idx >= BGR * EMB) return;
    int b = idx / EMB, j = idx % EMB;
    float acc = __ldg(me1_b + j) + __ldg(me2 + (size_t)__ldg(metal_type + b) * EMB + j);
#pragma unroll
    for (int k = 0; k < 17; k++)
        acc = fmaf(__ldg(metal_feat + (size_t)b * 17 + k), __ldg(me1_w + (size_t)j * 17 + k), acc);
    g_mf[idx] = acc;
}

// ---------------- transpose readout weights ----------------
__global__ void k_transpose_all(const float* __restrict__ wq, const float* __restrict__ wv,
                                const float* __restrict__ ml, const float* __restrict__ lg,
                                const float* __restrict__ ph1)
{
    int idx = blockIdx.x * blockDim.x + threadIdx.x;
    const int SZ1 = DK * EMB;
    if (idx < 4 * SZ1) {
        int w = idx / SZ1, i = idx % SZ1;
        int d = i / EMB, j = i % EMB;
        float v = (w == 0) ? wq[i] : (w == 1) ? wv[i] : (w == 2) ? ml[i] : lg[i];
        float* dst = (w == 0) ? g_wqt : (w == 1) ? g_wvt : (w == 2) ? g_mlt : g_lgt;
        dst[(size_t)j * DK + d] = v;
    } else {
        int i = idx - 4 * SZ1;
        if (i < 512 * DK) {
            int o = i / DK, d = i % DK;
            g_ph1t[(size_t)d * 512 + o] = ph1[i];
        }
    }
}

// ---------------- all layers' edge vectors in one kernel ----------------
__global__ void k_ve_all(const float* __restrict__ ew1, const float* __restrict__ mlp_w)
{
    int o = (blockIdx.x * blockDim.x + threadIdx.x) >> 5;
    if (o >= NLAYERS * 2 * EMB) return;
    int lane = threadIdx.x & 31;
    int l = o / (2 * EMB);
    int rem = o % (2 * EMB);
    int w = rem / EMB, col = rem % EMB;
    const float* e = ew1 + (size_t)l * 2 * EMB + (size_t)w * EMB;
    const float* wr = mlp_w + (size_t)l * EMB * EMB + (size_t)col * EMB;
    float s = 0.f;
    for (int k = lane; k < EMB; k += 32) s = fmaf(__ldg(e + k), __ldg(wr + k), s);
#pragma unroll
    for (int off = 16; off; off >>= 1) s += __shfl_xor_sync(0xffffffffu, s, off);
    if (lane == 0) g_ve_all[o] = s;
}

// ---------------- CSR build ----------------
__global__ void k_deg_init() {
    int i = blockIdx.x * blockDim.x + threadIdx.x;
    if (i < NNODES) g_deg[i] = 1;  // self-loop
}
__global__ void k_deg_count(const int* __restrict__ eidx) {
    int e = blockIdx.x * blockDim.x + threadIdx.x;
    if (e < NEDGES) atomicAdd(&g_deg[__ldg(eidx + NEDGES + e)], 1);
}
__global__ void k_scan() {
    __shared__ int ps[1024];
    const int C = (NNODES + 1023) / 1024;  // 49
    int t = threadIdx.x;
    int base = t * C;
    int s = 0;
    for (int i = base; i < base + C && i < NNODES; i++) s += g_deg[i];
    ps[t] = s;
    __syncthreads();
    for (int off = 1; off < 1024; off <<= 1) {
        int v = (t >= off) ? ps[t - off] : 0;
        __syncthreads();
        ps[t] += v;
        __syncthreads();
    }
    int ex = (t == 0) ? 0 : ps[t - 1];
    for (int i = base; i < base + C && i < NNODES; i++) {
        g_off[i] = ex; g_cur[i] = ex;
        ex += g_deg[i];
    }
    if (t == 1023) g_off[NNODES] = TOTE;
}
__global__ void k_fill(const int* __restrict__ eidx, const float* __restrict__ eattr) {
    int idx = blockIdx.x * blockDim.x + threadIdx.x;
    if (idx >= TOTE) return;
    int src, col; float2 ea;
    if (idx < NEDGES) {
        src = __ldg(eidx + idx);
        col = __ldg(eidx + NEDGES + idx);
        ea = __ldg((const float2*)eattr + idx);
    } else {
        src = col = idx - NEDGES;
        ea = make_float2(0.f, 4.f);
    }
    int pos = atomicAdd(&g_cur[col], 1);
    g_csr_src[pos] = src;
    g_csr_ea[pos] = ea;
}

// ---------------- GEMM: hW = h @ W.T + b   (3-pass bf16 split, tensor cores) ----
#define GBM 64
#define GBN 160
#define GBK 32
#define SKP 40   // padded k-stride in smem (bf16 elements)

#define MMA_BF16(d, a, b) asm volatile( \
    "mma.sync.aligned.m16n8k16.row.col.f32.bf16.bf16.f32 " \
    "{%0,%1,%2,%3},{%4,%5,%6,%7},{%8,%9},{%0,%1,%2,%3};\n" \
    : "+f"(d[0]), "+f"(d[1]), "+f"(d[2]), "+f"(d[3]) \
    : "r"(a[0]), "r"(a[1]), "r"(a[2]), "r"(a[3]), "r"(b[0]), "r"(b[1]))

__global__ void __launch_bounds__(256) k_gemm(const float* __restrict__ Wm,
                                              const float* __restrict__ bias)
{
    __shared__ __nv_bfloat16 As_hi[GBM][SKP], As_lo[GBM][SKP];
    __shared__ __nv_bfloat16 Bs_hi[GBN][SKP], Bs_lo[GBN][SKP];

    int m0 = blockIdx.x * GBM;
    int j0 = blockIdx.y * GBN;
    int tid = threadIdx.x;
    int warp = tid >> 5, lane = tid & 31;
    int gid = lane >> 2, tig = lane & 3;
    int wm = warp & 1, wn = warp >> 1;   // 2 (M) x 4 (N)
    int mb = wm * 32, nb = wn * 40;

    float acc[2][5][4];
#pragma unroll
    for (int mi = 0; mi < 2; mi++)
#pragma unroll
        for (int nj = 0; nj < 5; nj++)
#pragma unroll
            for (int r = 0; r < 4; r++) acc[mi][nj][r] = 0.f;

    for (int k0 = 0; k0 < 320; k0 += GBK) {
        // load A tile: 64 x 32 floats = 512 float4 -> 2 per thread
#pragma unroll
        for (int it = 0; it < 2; it++) {
            int f = tid + it * 256;
            int r = f >> 3, c4 = f & 7;
            int m = m0 + r, k = k0 + c4 * 4;
            float4 v = make_float4(0.f, 0.f, 0.f, 0.f);
            if (m < NNODES && k < 300)
                v = *(const float4*)(g_h + (size_t)m * EMB + k);
            float vs[4] = {v.x, v.y, v.z, v.w};
#pragma unroll
            for (int q = 0; q < 4; q++) {
                __nv_bfloat16 hv = __float2bfloat16(vs[q]);
                As_hi[r][c4 * 4 + q] = hv;
                As_lo[r][c4 * 4 + q] = __float2bfloat16(vs[q] - __bfloat162float(hv));
            }
        }
        // load B tile: 160 x 32 floats = 1280 float4 -> 5 per thread (Bs[j][k] = W[j][k])
#pragma unroll
        for (int it = 0; it < 5; it++) {
            int f = tid + it * 256;
            int r = f >> 3, c4 = f & 7;
            int j = j0 + r, k = k0 + c4 * 4;
            float4 v = make_float4(0.f, 0.f, 0.f, 0.f);
            if (j < 300 && k < 300)
                v = *(const float4*)(Wm + (size_t)j * EMB + k);
            float vs[4] = {v.x, v.y, v.z, v.w};
#pragma unroll
            for (int q = 0; q < 4; q++) {
                __nv_bfloat16 hv = __float2bfloat16(vs[q]);
                Bs_hi[r][c4 * 4 + q] = hv;
                Bs_lo[r][c4 * 4 + q] = __float2bfloat16(vs[q] - __bfloat162float(hv));
            }
        }
        __syncthreads();

#pragma unroll
        for (int ks = 0; ks < 2; ks++) {
            int kb = ks * 16;
            uint32_t ah[2][4], bh[5][2];
#pragma unroll
            for (int mi = 0; mi < 2; mi++) {
                int m = mb + mi * 16 + gid;
                ah[mi][0] = *(const uint32_t*)&As_hi[m][kb + 2 * tig];
                ah[mi][1] = *(const uint32_t*)&As_hi[m + 8][kb + 2 * tig];
                ah[mi][2] = *(const uint32_t*)&As_hi[m][kb + 8 + 2 * tig];
                ah[mi][3] = *(const uint32_t*)&As_hi[m + 8][kb + 8 + 2 * tig];
            }
#pragma unroll
            for (int nj = 0; nj < 5; nj++) {
                int n = nb + nj * 8 + gid;
                bh[nj][0] = *(const uint32_t*)&Bs_hi[n][kb + 2 * tig];
                bh[nj][1] = *(const uint32_t*)&Bs_hi[n][kb + 8 + 2 * tig];
            }
#pragma unroll
            for (int mi = 0; mi < 2; mi++)
#pragma unroll
                for (int nj = 0; nj < 5; nj++) MMA_BF16(acc[mi][nj], ah[mi], bh[nj]);
            // a_lo x b_hi
            {
                uint32_t al[2][4];
#pragma unroll
                for (int mi = 0; mi < 2; mi++) {
                    int m = mb + mi * 16 + gid;
                    al[mi][0] = *(const uint32_t*)&As_lo[m][kb + 2 * tig];
                    al[mi][1] = *(const uint32_t*)&As_lo[m + 8][kb + 2 * tig];
                    al[mi][2] = *(const uint32_t*)&As_lo[m][kb + 8 + 2 * tig];
                    al[mi][3] = *(const uint32_t*)&As_lo[m + 8][kb + 8 + 2 * tig];
                }
#pragma unroll
                for (int mi = 0; mi < 2; mi++)
#pragma unroll
                    for (int nj = 0; nj < 5; nj++) MMA_BF16(acc[mi][nj], al[mi], bh[nj]);
            }
            // a_hi x b_lo
            {
                uint32_t bl[5][2];
#pragma unroll
                for (int nj = 0; nj < 5; nj++) {
                    int n = nb + nj * 8 + gid;
                    bl[nj][0] = *(const uint32_t*)&Bs_lo[n][kb + 2 * tig];
                    bl[nj][1] = *(const uint32_t*)&Bs_lo[n][kb + 8 + 2 * tig];
                }
#pragma unroll
                for (int mi = 0; mi < 2; mi++)
#pragma unroll
                    for (int nj = 0; nj < 5; nj++) MMA_BF16(acc[mi][nj], ah[mi], bl[nj]);
            }
        }
        __syncthreads();
    }

    // epilogue
#pragma unroll
    for (int mi = 0; mi < 2; mi++) {
        int m = m0 + mb + mi * 16 + gid;
#pragma unroll
        for (int nj = 0; nj < 5; nj++) {
            int j = j0 + nb + nj * 8 + 2 * tig;
            if (j < 300) {
                float b0 = __ldg(bias + j), b1 = __ldg(bias + j + 1);
                if (m < NNODES) {
                    float2 o = make_float2(acc[mi][nj][0] + b0, acc[mi][nj][1] + b1);
                    *(float2*)(g_hW + (size_t)m * EMB + j) = o;
                }
                if (m + 8 < NNODES) {
                    float2 o = make_float2(acc[mi][nj][2] + b0, acc[mi][nj][3] + b1);
                    *(float2*)(g_hW + (size_t)(m + 8) * EMB + j) = o;
                }
            }
        }
    }
}

// ---------------- pull aggregation + BN (+relu), fused ----------------
// NOTE: layer index passed by value; g_ve_all indexed in DEVICE code
// (host-side arithmetic on a __device__ symbol was the R2 bug).
__global__ void __launch_bounds__(256) k_aggr(int layer,
                                              const float* __restrict__ rm,
                                              const float* __restrict__ rv,
                                              const float* __restrict__ gg,
                                              const float* __restrict__ bb,
                                              int do_relu)
{
    int gw = (blockIdx.x * blockDim.x + threadIdx.x) >> 5;
    if (gw >= NNODES) return;
    int lane = threadIdx.x & 31;
    const float4* ve4 = (const float4*)(g_ve_all + (size_t)layer * 2 * EMB);

    float4 acc[3], e0[3], e1[3];
#pragma unroll
    for (int i = 0; i < 3; i++) {
        acc[i] = make_float4(0.f, 0.f, 0.f, 0.f);
        int c = lane + 32 * i;
        if (c < EMB4) { e0[i] = __ldg(ve4 + c); e1[i] = __ldg(ve4 + EMB4 + c); }
    }
    int beg = g_off[gw], end = g_off[gw + 1];
    for (int e = beg; e < end; e++) {
        int src = g_csr_src[e];
        float2 ea = g_csr_ea[e];
        const float4* row = (const float4*)(g_hW + (size_t)src * EMB);
#pragma unroll
        for (int i = 0; i < 3; i++) {
            int c = lane + 32 * i;
            if (c < EMB4) {
                float4 x = row[c];
                acc[i].x += fmaxf(fmaf(ea.y, e1[i].x, fmaf(ea.x, e0[i].x, x.x)), 0.f);
                acc[i].y += fmaxf(fmaf(ea.y, e1[i].y, fmaf(ea.x, e0[i].y, x.y)), 0.f);
                acc[i].z += fmaxf(fmaf(ea.y, e1[i].z, fmaf(ea.x, e0[i].z, x.z)), 0.f);
                acc[i].w += fmaxf(fmaf(ea.y, e1[i].w, fmaf(ea.x, e0[i].w, x.w)), 0.f);
            }
        }
    }
    float4* hrow = (float4*)(g_h + (size_t)gw * EMB);
#pragma unroll
    for (int i = 0; i < 3; i++) {
        int c = lane + 32 * i;
        if (c < EMB4) {
            float4 m = __ldg((const float4*)rm + c);
            float4 v = __ldg((const float4*)rv + c);
            float4 g4 = __ldg((const float4*)gg + c);
            float4 b4 = __ldg((const float4*)bb + c);
            float4 y;
            y.x = (acc[i].x - m.x) * rsqrtf(v.x + 1e-5f) * g4.x + b4.x;
            y.y = (acc[i].y - m.y) * rsqrtf(v.y + 1e-5f) * g4.y + b4.y;
            y.z = (acc[i].z - m.z) * rsqrtf(v.z + 1e-5f) * g4.z + b4.z;
            y.w = (acc[i].w - m.w) * rsqrtf(v.w + 1e-5f) * g4.w + b4.w;
            if (do_relu) {
                y.x = fmaxf(y.x, 0.f); y.y = fmaxf(y.y, 0.f);
                y.z = fmaxf(y.z, 0.f); y.w = fmaxf(y.w, 0.f);
            }
            hrow[c] = y;
        }
    }
}

// ---------------- readout ----------------
__global__ void k_q()
{
    __shared__ float mfs[4][EMB];
    int b0 = blockIdx.x * 4, tid = threadIdx.x;
    for (int i = tid; i < 4 * EMB; i += 256)
        mfs[i / EMB][i % EMB] = g_mf[(size_t)(b0 + i / EMB) * EMB + i % EMB];
    __syncthreads();
    float acc[4] = {0.f, 0.f, 0.f, 0.f};
    for (int j = 0; j < EMB; j++) {
        float w = g_wqt[(size_t)j * DK + tid];
#pragma unroll
        for (int g = 0; g < 4; g++) acc[g] = fmaf(mfs[g][j], w, acc[g]);
    }
#pragma unroll
    for (int g = 0; g < 4; g++) g_Q[(size_t)(b0 + g) * DK + tid] = acc[g];
}

__global__ void k_qk(const float* __restrict__ wk)
{
    __shared__ float Qs[4][DK];
    int b0 = blockIdx.x * 4, tid = threadIdx.x;
    for (int i = tid; i < 4 * DK; i += 320)
        Qs[i / DK][i % DK] = g_Q[(size_t)(b0 + i / DK) * DK + i % DK];
    __syncthreads();
    if (tid < EMB) {
        float acc[4] = {0.f, 0.f, 0.f, 0.f};
        for (int d = 0; d < DK; d++) {
            float w = __ldg(wk + (size_t)d * EMB + tid);
#pragma unroll
            for (int g = 0; g < 4; g++) acc[g] = fmaf(Qs[g][d], w, acc[g]);
        }
#pragma unroll
        for (int g = 0; g < 4; g++) g_qk[(size_t)(b0 + g) * EMB + tid] = acc[g];
    }
}

__global__ void k_attn()
{
    __shared__ float qks[EMB];
    __shared__ float sc[NPER];
    __shared__ float p[NPER];
    int b = blockIdx.x, tid = threadIdx.x;
    for (int i = tid; i < EMB; i += 256) qks[i] = g_qk[(size_t)b * EMB + i];
    __syncthreads();
    int warp = tid >> 5, lane = tid & 31;
    const float* hb = g_h + (size_t)b * NPER * EMB;
    for (int k = warp; k < NPER; k += 8) {
        float s = 0.f;
        for (int i = lane; i < EMB; i += 32) s = fmaf(qks[i], hb[(size_t)k * EMB + i], s);
#pragma unroll
        for (int off = 16; off; off >>= 1) s += __shfl_xor_sync(0xffffffffu, s, off);
        if (lane == 0) sc[k] = s * (1.0f / 16.0f);
    }
    __syncthreads();
    if (tid == 0) {
        float mx = -1e30f;
        for (int k = 0; k < NPER; k++) mx = fmaxf(mx, sc[k]);
        float ssum = 0.f;
        for (int k = 0; k < NPER; k++) { float e = expf(sc[k] - mx); p[k] = e; ssum += e; }
        float inv = 1.f / ssum;
        for (int k = 0; k < NPER; k++) p[k] *= inv;
    }
    __syncthreads();
    for (int j = tid; j < EMB; j += 256) {
        float ws = 0.f, mn = 0.f;
        for (int k = 0; k < NPER; k++) {
            float v = hb[(size_t)k * EMB + j];
            ws = fmaf(p[k], v, ws); mn += v;
        }
        g_wsum[(size_t)b * EMB + j] = ws;
        g_mean[(size_t)b * EMB + j] = mn * (1.0f / NPER);
    }
}

__global__ void k_final(const float* __restrict__ ml_b, const float* __restrict__ lg_b,
                        const float* __restrict__ ph1_b, const float* __restrict__ ph2_w,
                        const float* __restrict__ ph2_b, float* __restrict__ out)
{
    __shared__ float ws[4][EMB], mfs[4][EMB], mns[4][EMB];
    __shared__ float feat[4][DK];
    __shared__ float red[256];
    int b0 = blockIdx.x * 4, tid = threadIdx.x;
    for (int i = tid; i < 4 * EMB; i += 256) {
        int g = i / EMB, j = i % EMB;
        ws[g][j]  = g_wsum[(size_t)(b0 + g) * EMB + j];
        mfs[g][j] = g_mf[(size_t)(b0 + g) * EMB + j];
        mns[g][j] = g_mean[(size_t)(b0 + g) * EMB + j];
    }
    __syncthreads();
    int d = tid;
    float a[4], m2[4], lg[4];
    float mb = __ldg(ml_b + d), lb = __ldg(lg_b + d);
#pragma unroll
    for (int g = 0; g < 4; g++) { a[g] = 0.f; m2[g] = mb; lg[g] = lb; }
    for (int k = 0; k < EMB; k++) {
        float wv_ = g_wvt[(size_t)k * DK + d];
        float ml_ = g_mlt[(size_t)k * DK + d];
        float lg_ = g_lgt[(size_t)k * DK + d];
#pragma unroll
        for (int g = 0; g < 4; g++) {
            a[g]  = fmaf(wv_, ws[g][k],  a[g]);
            m2[g] = fmaf(ml_, mfs[g][k], m2[g]);
            lg[g] = fmaf(lg_, mns[g][k], lg[g]);
        }
    }
#pragma unroll
    for (int g = 0; g < 4; g++)
        feat[g][d] = fmaxf(a[g], 0.f) + fmaxf(m2[g], 0.f) + fmaxf(lg[g], 0.f);
    __syncthreads();
    float part[4] = {0.f, 0.f, 0.f, 0.f};
#pragma unroll
    for (int rep = 0; rep < 2; rep++) {
        int o = tid + rep * 256;
        float t[4];
        float pb = __ldg(ph1_b + o);
#pragma unroll
        for (int g = 0; g < 4; g++) t[g] = pb;
        for (int k = 0; k < DK; k++) {
            float w = g_ph1t[(size_t)k * 512 + o];
#pragma unroll
            for (int g = 0; g < 4; g++) t[g] = fmaf(w, feat[g][k], t[g]);
        }
        float p2 = __ldg(ph2_w + o);
#pragma unroll
        for (int g = 0; g < 4; g++) {
            float x = t[g];
            float sp = (x > 20.f) ? x : log1pf(expf(x));
            part[g] = fmaf(sp, p2, part[g]);
        }
    }
    for (int g = 0; g < 4; g++) {
        red[tid] = part[g];
        __syncthreads();
        for (int s = 128; s; s >>= 1) {
            if (tid < s) red[tid] += red[tid + s];
            __syncthreads();
        }
        if (tid == 0) out[b0 + g] = red[0] + __ldg(ph2_b);
        __syncthreads();
    }
}

// ---------------- launch ----------------
extern "C" void kernel_launch(void* const* d_in, const int* in_sizes, int n_in,
                              void* d_out, int out_size)
{
    const int*   x_type     = (const int*)d_in[0];
    const float* x_feat     = (const float*)d_in[1];
    const int*   edge_index = (const int*)d_in[2];
    const float* edge_attr  = (const float*)d_in[3];
    const int*   metal_type = (const int*)d_in[4];
    const float* metal_feat = (const float*)d_in[5];
    const float* x_emb      = (const float*)d_in[6];
    const float* x_weight   = (const float*)d_in[7];
    const float* ew1        = (const float*)d_in[8];
    const float* mlp_w      = (const float*)d_in[9];
    const float* mlp_b      = (const float*)d_in[10];
    const float* bn_g       = (const float*)d_in[11];
    const float* bn_b       = (const float*)d_in[12];
    const float* bn_rm      = (const float*)d_in[13];
    const float* bn_rv      = (const float*)d_in[14];
    const float* me1_w      = (const float*)d_in[15];
    const float* me1_b      = (const float*)d_in[16];
    const float* me2        = (const float*)d_in[17];
    const float* wq         = (const float*)d_in[18];
    const float* wk         = (const float*)d_in[19];
    const float* wv         = (const float*)d_in[20];
    const float* ml_w       = (const float*)d_in[21];
    const float* ml_b       = (const float*)d_in[22];
    const float* lg_w       = (const float*)d_in[23];
    const float* lg_b       = (const float*)d_in[24];
    const float* ph1_w      = (const float*)d_in[25];
    const float* ph1_b      = (const float*)d_in[26];
    const float* ph2_w      = (const float*)d_in[27];
    const float* ph2_b      = (const float*)d_in[28];
    float* out = (float*)d_out;

    k_init<<<(NNODES * EMB4 + 255) / 256, 256>>>(x_type, x_feat, x_emb, x_weight);
    k_mf<<<(BGR * EMB + 255) / 256, 256>>>(metal_type, metal_feat, me1_w, me1_b, me2);
    k_transpose_all<<<(4 * DK * EMB + 512 * DK + 255) / 256, 256>>>(wq, wv, ml_w, lg_w, ph1_w);
    k_ve_all<<<(NLAYERS * 2 * EMB * 32 + 255) / 256, 256>>>(ew1, mlp_w);

    // CSR build (once per launch)
    k_deg_init<<<(NNODES + 255) / 256, 256>>>();
    k_deg_count<<<(NEDGES + 255) / 256, 256>>>(edge_index);
    k_scan<<<1, 1024>>>();
    k_fill<<<(TOTE + 255) / 256, 256>>>(edge_index, edge_attr);

    for (int l = 0; l < NLAYERS; l++) {
        const float* Wl = mlp_w + (size_t)l * EMB * EMB;
        dim3 gg((NNODES + GBM - 1) / GBM, 2);
        k_gemm<<<gg, 256>>>(Wl, mlp_b + (size_t)l * EMB);
        k_aggr<<<(NNODES * 32 + 255) / 256, 256>>>(
            l,
            bn_rm + (size_t)l * EMB, bn_rv + (size_t)l * EMB,
            bn_g + (size_t)l * EMB, bn_b + (size_t)l * EMB,
            l < NLAYERS - 1 ? 1 : 0);
    }

    k_q<<<BGR / 4, 256>>>();
    k_qk<<<BGR / 4, 320>>>(wk);
    k_attn<<<BGR, 256>>>();
    k_final<<<BGR / 4, 256>>>(ml_b, lg_b, ph1_b, ph2_w, ph2_b, out);
}

// round 5
// speedup vs baseline: 1.5712x; 1.1624x over previous
#include <cuda_runtime.h>
#include <cuda_bf16.h>
#include <math.h>
#include <stdint.h>

#define NNODES 50000
#define NPADM  50048
#define NEDGES 200000
#define TOTE   (NEDGES + NNODES)
#define EMB    300
#define EMB4   75
#define KPAD   320
#define DK     256
#define BGR    1000
#define NPER   50
#define NLAYERS 5
#define PADF   16

// ---------------- scratch (device globals) ----------------
__device__ float g_h[NNODES * EMB];
__device__ float g_hW[NNODES * EMB];
__device__ __nv_bfloat16 g_hs_hi[NPADM * KPAD];
__device__ __nv_bfloat16 g_hs_lo[NPADM * KPAD];
__device__ __nv_bfloat16 g_ws_hi[NLAYERS * KPAD * KPAD];
__device__ __nv_bfloat16 g_ws_lo[NLAYERS * KPAD * KPAD];
__device__ float g_mf[BGR * EMB];
__device__ float g_ve_all[NLAYERS * 2 * EMB];
__device__ float g_Q[BGR * DK];
__device__ float g_qk[BGR * EMB];
__device__ float g_wsum[BGR * EMB];
__device__ float g_mean[BGR * EMB];
__device__ float g_wqt[EMB * DK];
__device__ float g_wvt[EMB * DK];
__device__ float g_mlt[EMB * DK];
__device__ float g_lgt[EMB * DK];
__device__ float g_ph1t[DK * 512];
// CSR
__device__ int g_deg[NNODES];
__device__ int g_off[NNODES + 1];
__device__ int g_cur[NNODES];
__device__ int g_csr_src[TOTE];
__device__ float2 g_csr_ea[TOTE];

// ---------------- helpers ----------------
__device__ __forceinline__ void store_split4(__nv_bfloat16* hh, __nv_bfloat16* hl, float4 v)
{
    float a[4] = {v.x, v.y, v.z, v.w};
    __nv_bfloat16 h[4], l[4];
#pragma unroll
    for (int q = 0; q < 4; q++) {
        h[q] = __float2bfloat16(a[q]);
        l[q] = __float2bfloat16(a[q] - __bfloat162float(h[q]));
    }
    *(__nv_bfloat162*)(hh)     = __halves2bfloat162(h[0], h[1]);
    *(__nv_bfloat162*)(hh + 2) = __halves2bfloat162(h[2], h[3]);
    *(__nv_bfloat162*)(hl)     = __halves2bfloat162(l[0], l[1]);
    *(__nv_bfloat162*)(hl + 2) = __halves2bfloat162(l[2], l[3]);
}

__device__ __forceinline__ uint32_t smem_u32(const void* p) {
    uint32_t a;
    asm("{ .reg .u64 t; cvta.to.shared.u64 t, %1; cvt.u32.u64 %0, t; }" : "=r"(a) : "l"(p));
    return a;
}

#define MMA_BF16(d, a, b) asm volatile( \
    "mma.sync.aligned.m16n8k16.row.col.f32.bf16.bf16.f32 " \
    "{%0,%1,%2,%3},{%4,%5,%6,%7},{%8,%9},{%0,%1,%2,%3};\n" \
    : "+f"(d[0]), "+f"(d[1]), "+f"(d[2]), "+f"(d[3]) \
    : "r"(a[0]), "r"(a[1]), "r"(a[2]), "r"(a[3]), "r"(b[0]), "r"(b[1]))

#define LDM4(r, a) asm volatile( \
    "ldmatrix.sync.aligned.m8n8.x4.shared.b16 {%0,%1,%2,%3}, [%4];" \
    : "=r"((r)[0]), "=r"((r)[1]), "=r"((r)[2]), "=r"((r)[3]) : "r"(a))
#define LDM2(r, a) asm volatile( \
    "ldmatrix.sync.aligned.m8n8.x2.shared.b16 {%0,%1}, [%2];" \
    : "=r"((r)[0]), "=r"((r)[1]) : "r"(a))
#define CPA16(dst, src) asm volatile( \
    "cp.async.cg.shared.global [%0], [%1], 16;" :: "r"(dst), "l"(src) : "memory")

// ---------------- node init (+ bf16 split write) ----------------
__global__ void k_init(const int* __restrict__ x_type, const float* __restrict__ x_feat,
                       const float* __restrict__ x_emb, const float* __restrict__ x_weight)
{
    int idx = blockIdx.x * blockDim.x + threadIdx.x;
    if (idx >= NNODES * EMB4) return;
    int n = idx / EMB4, c = idx % EMB4;
    int t = __ldg(x_type + n);
    float4 acc = __ldg((const float4*)(x_emb + (size_t)t * EMB) + c);
#pragma unroll
    for (int k = 0; k < PADF; k++) {
        float f = __ldg(x_feat + (size_t)n * PADF + k);
        float4 w = __ldg((const float4*)(x_weight + (size_t)k * EMB) + c);
        acc.x = fmaf(f, w.x, acc.x); acc.y = fmaf(f, w.y, acc.y);
        acc.z = fmaf(f, w.z, acc.z); acc.w = fmaf(f, w.w, acc.w);
    }
    ((float4*)g_h)[idx] = acc;
    store_split4(g_hs_hi + (size_t)n * KPAD + c * 4, g_hs_lo + (size_t)n * KPAD + c * 4, acc);
    if (c == 74) {  // zero pad cols 300..319
        __nv_bfloat162 z = __floats2bfloat162_rn(0.f, 0.f);
#pragma unroll
        for (int q = 0; q < 10; q++) {
            ((__nv_bfloat162*)(g_hs_hi + (size_t)n * KPAD + 300))[q] = z;
            ((__nv_bfloat162*)(g_hs_lo + (size_t)n * KPAD + 300))[q] = z;
        }
    }
}

// ---------------- weight split (all layers, once) ----------------
__global__ void k_wsplit(const float* __restrict__ mlp_w)
{
    int idx = blockIdx.x * blockDim.x + threadIdx.x;
    if (idx >= NLAYERS * KPAD * KPAD) return;
    int l = idx / (KPAD * KPAD), rem = idx % (KPAD * KPAD);
    int j = rem / KPAD, k = rem % KPAD;
    float v = (j < EMB && k < EMB) ? __ldg(mlp_w + (size_t)l * EMB * EMB + (size_t)j * EMB + k) : 0.f;
    __nv_bfloat16 hi = __float2bfloat16(v);
    g_ws_hi[idx] = hi;
    g_ws_lo[idx] = __float2bfloat16(v - __bfloat162float(hi));
}

// ---------------- metal feature ----------------
__global__ void k_mf(const int* __restrict__ metal_type, const float* __restrict__ metal_feat,
                     const float* __restrict__ me1_w, const float* __restrict__ me1_b,
                     const float* __restrict__ me2)
{
    int idx = blockIdx.x * blockDim.x + threadIdx.x;
    if (idx >= BGR * EMB) return;
    int b = idx / EMB, j = idx % EMB;
    float acc = __ldg(me1_b + j) + __ldg(me2 + (size_t)__ldg(metal_type + b) * EMB + j);
#pragma unroll
    for (int k = 0; k < 17; k++)
        acc = fmaf(__ldg(metal_feat + (size_t)b * 17 + k), __ldg(me1_w + (size_t)j * 17 + k), acc);
    g_mf[idx] = acc;
}

// ---------------- transpose readout weights ----------------
__global__ void k_transpose_all(const float* __restrict__ wq, const float* __restrict__ wv,
                                const float* __restrict__ ml, const float* __restrict__ lg,
                                const float* __restrict__ ph1)
{
    int idx = blockIdx.x * blockDim.x + threadIdx.x;
    const int SZ1 = DK * EMB;
    if (idx < 4 * SZ1) {
        int w = idx / SZ1, i = idx % SZ1;
        int d = i / EMB, j = i % EMB;
        float v = (w == 0) ? wq[i] : (w == 1) ? wv[i] : (w == 2) ? ml[i] : lg[i];
        float* dst = (w == 0) ? g_wqt : (w == 1) ? g_wvt : (w == 2) ? g_mlt : g_lgt;
        dst[(size_t)j * DK + d] = v;
    } else {
        int i = idx - 4 * SZ1;
        if (i < 512 * DK) {
            int o = i / DK, d = i % DK;
            g_ph1t[(size_t)d * 512 + o] = ph1[i];
        }
    }
}

// ---------------- all layers' edge vectors ----------------
__global__ void k_ve_all(const float* __restrict__ ew1, const float* __restrict__ mlp_w)
{
    int o = (blockIdx.x * blockDim.x + threadIdx.x) >> 5;
    if (o >= NLAYERS * 2 * EMB) return;
    int lane = threadIdx.x & 31;
    int l = o / (2 * EMB);
    int rem = o % (2 * EMB);
    int w = rem / EMB, col = rem % EMB;
    const float* e = ew1 + (size_t)l * 2 * EMB + (size_t)w * EMB;
    const float* wr = mlp_w + (size_t)l * EMB * EMB + (size_t)col * EMB;
    float s = 0.f;
    for (int k = lane; k < EMB; k += 32) s = fmaf(__ldg(e + k), __ldg(wr + k), s);
#pragma unroll
    for (int off = 16; off; off >>= 1) s += __shfl_xor_sync(0xffffffffu, s, off);
    if (lane == 0) g_ve_all[o] = s;
}

// ---------------- CSR build ----------------
__global__ void k_deg_init() {
    int i = blockIdx.x * blockDim.x + threadIdx.x;
    if (i < NNODES) g_deg[i] = 1;
}
__global__ void k_deg_count(const int* __restrict__ eidx) {
    int e = blockIdx.x * blockDim.x + threadIdx.x;
    if (e < NEDGES) atomicAdd(&g_deg[__ldg(eidx + NEDGES + e)], 1);
}
__global__ void k_scan() {
    __shared__ int ps[1024];
    const int C = (NNODES + 1023) / 1024;
    int t = threadIdx.x;
    int base = t * C;
    int s = 0;
    for (int i = base; i < base + C && i < NNODES; i++) s += g_deg[i];
    ps[t] = s;
    __syncthreads();
    for (int off = 1; off < 1024; off <<= 1) {
        int v = (t >= off) ? ps[t - off] : 0;
        __syncthreads();
        ps[t] += v;
        __syncthreads();
    }
    int ex = (t == 0) ? 0 : ps[t - 1];
    for (int i = base; i < base + C && i < NNODES; i++) {
        g_off[i] = ex; g_cur[i] = ex;
        ex += g_deg[i];
    }
    if (t == 1023) g_off[NNODES] = TOTE;
}
__global__ void k_fill(const int* __restrict__ eidx, const float* __restrict__ eattr) {
    int idx = blockIdx.x * blockDim.x + threadIdx.x;
    if (idx >= TOTE) return;
    int src, col; float2 ea;
    if (idx < NEDGES) {
        src = __ldg(eidx + idx);
        col = __ldg(eidx + NEDGES + idx);
        ea = __ldg((const float2*)eattr + idx);
    } else {
        src = col = idx - NEDGES;
        ea = make_float2(0.f, 4.f);
    }
    int pos = atomicAdd(&g_cur[col], 1);
    g_csr_src[pos] = src;
    g_csr_ea[pos] = ea;
}

// ---------------- GEMM: hW = h @ W.T + b (3-pass bf16 split, mma.sync + ldmatrix) ---
// CTA tile 128(M) x 160(N), K chunks of 64, double-buffered cp.async.
// smem per stage: A_hi 128x72x2=18432, A_lo 18432, B_hi 160x72x2=23040, B_lo 23040
#define SKPB   144            // 72 bf16 * 2 bytes, padded row stride
#define STG_A_LO 18432
#define STG_B    36864
#define STG_B_LO 23040
#define STG_SZ   82944
#define GEMM_SMEM (2 * STG_SZ)

__device__ __forceinline__ void gemm_prefetch(uint32_t sbase, int layer, int m0, int j0,
                                              int k0, int tid)
{
    // A: 128 rows x 64 cols bf16 = 1024 x16B per array
#pragma unroll
    for (int it = 0; it < 4; it++) {
        int f = tid + it * 256;
        int r = f >> 3, c4 = f & 7;
        uint32_t dst = sbase + r * SKPB + c4 * 16;
        const __nv_bfloat16* s0 = g_hs_hi + (size_t)(m0 + r) * KPAD + k0 + c4 * 8;
        const __nv_bfloat16* s1 = g_hs_lo + (size_t)(m0 + r) * KPAD + k0 + c4 * 8;
        CPA16(dst, s0);
        CPA16(dst + STG_A_LO, s1);
    }
    // B: 160 rows x 64 cols bf16 = 1280 x16B per array
#pragma unroll
    for (int it = 0; it < 5; it++) {
        int f = tid + it * 256;
        int r = f >> 3, c4 = f & 7;
        uint32_t dst = sbase + STG_B + r * SKPB + c4 * 16;
        size_t off = ((size_t)layer * KPAD + j0 + r) * KPAD + k0 + c4 * 8;
        CPA16(dst, g_ws_hi + off);
        CPA16(dst + STG_B_LO, g_ws_lo + off);
    }
    asm volatile("cp.async.commit_group;" ::: "memory");
}

__global__ void __launch_bounds__(256) k_gemm_mma(int layer, const float* __restrict__ bias)
{
    extern __shared__ char smem[];
    uint32_t sb = smem_u32(smem);
    int tid = threadIdx.x, warp = tid >> 5, lane = tid & 31;
    int gid = lane >> 2, tig = lane & 3;
    int wm = warp & 1, wn = warp >> 1;      // 2 (M) x 4 (N) warps
    int m0 = blockIdx.x * 128, j0 = blockIdx.y * 160;

    float acc[4][5][4];
#pragma unroll
    for (int mt = 0; mt < 4; mt++)
#pragma unroll
        for (int nj = 0; nj < 5; nj++)
#pragma unroll
            for (int r = 0; r < 4; r++) acc[mt][nj][r] = 0.f;

    // fragment addresses (constant across k-chunks except kb/stage offset)
    int arow = wm * 64 + (lane & 15);
    int acolB = 16 * (lane >> 4);           // bytes: 8 bf16 * 2 per half
    int brow4 = wn * 40 + 8 * (lane >> 4) + (lane & 7);
    int bcolB = 16 * ((lane >> 3) & 1);
    int brow2 = wn * 40 + 32 + (lane & 7);

    gemm_prefetch(sb, layer, m0, j0, 0, tid);

    for (int kc = 0; kc < 5; kc++) {
        int cur = kc & 1;
        asm volatile("cp.async.wait_group 0;" ::: "memory");
        __syncthreads();
        if (kc < 4)
            gemm_prefetch(sb + (1 - cur) * STG_SZ, layer, m0, j0, (kc + 1) * 64, tid);

        uint32_t Ab = sb + cur * STG_SZ;
        uint32_t Bb = Ab + STG_B;
#pragma unroll
        for (int ks = 0; ks < 4; ks++) {
            int kbB = ks * 32;              // 16 bf16 = 32 bytes
            uint32_t ah[4][4], al[4][4], bh[5][2], bl[5][2];
#pragma unroll
            for (int mt = 0; mt < 4; mt++) {
                uint32_t ad = Ab + (arow + mt * 16) * SKPB + kbB + acolB;
                LDM4(ah[mt], ad);
                LDM4(al[mt], ad + STG_A_LO);
            }
#pragma unroll
            for (int pr = 0; pr < 2; pr++) {
                uint32_t bd = Bb + (brow4 + pr * 16) * SKPB + kbB + bcolB;
                uint32_t t[4];
                LDM4(t, bd);
                bh[2 * pr][0] = t[0]; bh[2 * pr][1] = t[1];
                bh[2 * pr + 1][0] = t[2]; bh[2 * pr + 1][1] = t[3];
                LDM4(t, bd + STG_B_LO);
                bl[2 * pr][0] = t[0]; bl[2 * pr][1] = t[1];
                bl[2 * pr + 1][0] = t[2]; bl[2 * pr + 1][1] = t[3];
            }
            {
                uint32_t bd = Bb + brow2 * SKPB + kbB + bcolB;
                LDM2(bh[4], bd);
                LDM2(bl[4], bd + STG_B_LO);
            }
#pragma unroll
            for (int mt = 0; mt < 4; mt++)
#pragma unroll
                for (int nj = 0; nj < 5; nj++) MMA_BF16(acc[mt][nj], ah[mt], bh[nj]);
#pragma unroll
            for (int mt = 0; mt < 4; mt++)
#pragma unroll
                for (int nj = 0; nj < 5; nj++) MMA_BF16(acc[mt][nj], ah[mt], bl[nj]);
#pragma unroll
            for (int mt = 0; mt < 4; mt++)
#pragma unroll
                for (int nj = 0; nj < 5; nj++) MMA_BF16(acc[mt][nj], al[mt], bh[nj]);
        }
        __syncthreads();
    }

    // epilogue: + bias, store fp32
#pragma unroll
    for (int mt = 0; mt < 4; mt++) {
        int m = m0 + wm * 64 + mt * 16 + gid;
#pragma unroll
        for (int nj = 0; nj < 5; nj++) {
            int j = j0 + wn * 40 + nj * 8 + 2 * tig;
            if (j < EMB) {
                float b0 = __ldg(bias + j), b1 = __ldg(bias + j + 1);
                if (m < NNODES)
                    *(float2*)(g_hW + (size_t)m * EMB + j) =
                        make_float2(acc[mt][nj][0] + b0, acc[mt][nj][1] + b1);
                if (m + 8 < NNODES)
                    *(float2*)(g_hW + (size_t)(m + 8) * EMB + j) =
                        make_float2(acc[mt][nj][2] + b0, acc[mt][nj][3] + b1);
            }
        }
    }
}

// ---------------- pull aggregation + BN (+relu) + bf16 split, fused ----------------
__global__ void __launch_bounds__(256) k_aggr(int layer,
                                              const float* __restrict__ rm,
                                              const float* __restrict__ rv,
                                              const float* __restrict__ gg,
                                              const float* __restrict__ bb,
                                              int do_relu)
{
    int gw = (blockIdx.x * blockDim.x + threadIdx.x) >> 5;
    if (gw >= NNODES) return;
    int lane = threadIdx.x & 31;
    const float4* ve4 = (const float4*)(g_ve_all + (size_t)layer * 2 * EMB);

    float4 acc[3], e0[3], e1[3];
#pragma unroll
    for (int i = 0; i < 3; i++) {
        acc[i] = make_float4(0.f, 0.f, 0.f, 0.f);
        int c = lane + 32 * i;
        if (c < EMB4) { e0[i] = __ldg(ve4 + c); e1[i] = __ldg(ve4 + EMB4 + c); }
    }
    int beg = g_off[gw], end = g_off[gw + 1];
    for (int e = beg; e < end; e++) {
        int src = g_csr_src[e];
        float2 ea = g_csr_ea[e];
        const float4* row = (const float4*)(g_hW + (size_t)src * EMB);
#pragma unroll
        for (int i = 0; i < 3; i++) {
            int c = lane + 32 * i;
            if (c < EMB4) {
                float4 x = row[c];
                acc[i].x += fmaxf(fmaf(ea.y, e1[i].x, fmaf(ea.x, e0[i].x, x.x)), 0.f);
                acc[i].y += fmaxf(fmaf(ea.y, e1[i].y, fmaf(ea.x, e0[i].y, x.y)), 0.f);
                acc[i].z += fmaxf(fmaf(ea.y, e1[i].z, fmaf(ea.x, e0[i].z, x.z)), 0.f);
                acc[i].w += fmaxf(fmaf(ea.y, e1[i].w, fmaf(ea.x, e0[i].w, x.w)), 0.f);
            }
        }
    }
    float4* hrow = (float4*)(g_h + (size_t)gw * EMB);
#pragma unroll
    for (int i = 0; i < 3; i++) {
        int c = lane + 32 * i;
        if (c < EMB4) {
            float4 m = __ldg((const float4*)rm + c);
            float4 v = __ldg((const float4*)rv + c);
            float4 g4 = __ldg((const float4*)gg + c);
            float4 b4 = __ldg((const float4*)bb + c);
            float4 y;
            y.x = (acc[i].x - m.x) * rsqrtf(v.x + 1e-5f) * g4.x + b4.x;
            y.y = (acc[i].y - m.y) * rsqrtf(v.y + 1e-5f) * g4.y + b4.y;
            y.z = (acc[i].z - m.z) * rsqrtf(v.z + 1e-5f) * g4.z + b4.z;
            y.w = (acc[i].w - m.w) * rsqrtf(v.w + 1e-5f) * g4.w + b4.w;
            if (do_relu) {
                y.x = fmaxf(y.x, 0.f); y.y = fmaxf(y.y, 0.f);
                y.z = fmaxf(y.z, 0.f); y.w = fmaxf(y.w, 0.f);
            }
            hrow[c] = y;
            store_split4(g_hs_hi + (size_t)gw * KPAD + c * 4,
                         g_hs_lo + (size_t)gw * KPAD + c * 4, y);
        }
    }
}

// ---------------- readout ----------------
__global__ void k_q()
{
    __shared__ float mfs[4][EMB];
    int b0 = blockIdx.x * 4, tid = threadIdx.x;
    for (int i = tid; i < 4 * EMB; i += 256)
        mfs[i / EMB][i % EMB] = g_mf[(size_t)(b0 + i / EMB) * EMB + i % EMB];
    __syncthreads();
    float acc[4] = {0.f, 0.f, 0.f, 0.f};
    for (int j = 0; j < EMB; j++) {
        float w = g_wqt[(size_t)j * DK + tid];
#pragma unroll
        for (int g = 0; g < 4; g++) acc[g] = fmaf(mfs[g][j], w, acc[g]);
    }
#pragma unroll
    for (int g = 0; g < 4; g++) g_Q[(size_t)(b0 + g) * DK + tid] = acc[g];
}

__global__ void k_qk(const float* __restrict__ wk)
{
    __shared__ float Qs[4][DK];
    int b0 = blockIdx.x * 4, tid = threadIdx.x;
    for (int i = tid; i < 4 * DK; i += 320)
        Qs[i / DK][i % DK] = g_Q[(size_t)(b0 + i / DK) * DK + i % DK];
    __syncthreads();
    if (tid < EMB) {
        float acc[4] = {0.f, 0.f, 0.f, 0.f};
        for (int d = 0; d < DK; d++) {
            float w = __ldg(wk + (size_t)d * EMB + tid);
#pragma unroll
            for (int g = 0; g < 4; g++) acc[g] = fmaf(Qs[g][d], w, acc[g]);
        }
#pragma unroll
        for (int g = 0; g < 4; g++) g_qk[(size_t)(b0 + g) * EMB + tid] = acc[g];
    }
}

__global__ void k_attn()
{
    __shared__ float qks[EMB];
    __shared__ float sc[NPER];
    __shared__ float p[NPER];
    int b = blockIdx.x, tid = threadIdx.x;
    for (int i = tid; i < EMB; i += 256) qks[i] = g_qk[(size_t)b * EMB + i];
    __syncthreads();
    int warp = tid >> 5, lane = tid & 31;
    const float* hb = g_h + (size_t)b * NPER * EMB;
    for (int k = warp; k < NPER; k += 8) {
        float s = 0.f;
        for (int i = lane; i < EMB; i += 32) s = fmaf(qks[i], hb[(size_t)k * EMB + i], s);
#pragma unroll
        for (int off = 16; off; off >>= 1) s += __shfl_xor_sync(0xffffffffu, s, off);
        if (lane == 0) sc[k] = s * (1.0f / 16.0f);
    }
    __syncthreads();
    if (tid == 0) {
        float mx = -1e30f;
        for (int k = 0; k < NPER; k++) mx = fmaxf(mx, sc[k]);
        float ssum = 0.f;
        for (int k = 0; k < NPER; k++) { float e = expf(sc[k] - mx); p[k] = e; ssum += e; }
        float inv = 1.f / ssum;
        for (int k = 0; k < NPER; k++) p[k] *= inv;
    }
    __syncthreads();
    for (int j = tid; j < EMB; j += 256) {
        float ws = 0.f, mn = 0.f;
        for (int k = 0; k < NPER; k++) {
            float v = hb[(size_t)k * EMB + j];
            ws = fmaf(p[k], v, ws); mn += v;
        }
        g_wsum[(size_t)b * EMB + j] = ws;
        g_mean[(size_t)b * EMB + j] = mn * (1.0f / NPER);
    }
}

__global__ void k_final(const float* __restrict__ ml_b, const float* __restrict__ lg_b,
                        const float* __restrict__ ph1_b, const float* __restrict__ ph2_w,
                        const float* __restrict__ ph2_b, float* __restrict__ out)
{
    __shared__ float ws[4][EMB], mfs[4][EMB], mns[4][EMB];
    __shared__ float feat[4][DK];
    __shared__ float red[256];
    int b0 = blockIdx.x * 4, tid = threadIdx.x;
    for (int i = tid; i < 4 * EMB; i += 256) {
        int g = i / EMB, j = i % EMB;
        ws[g][j]  = g_wsum[(size_t)(b0 + g) * EMB + j];
        mfs[g][j] = g_mf[(size_t)(b0 + g) * EMB + j];
        mns[g][j] = g_mean[(size_t)(b0 + g) * EMB + j];
    }
    __syncthreads();
    int d = tid;
    float a[4], m2[4], lg[4];
    float mb = __ldg(ml_b + d), lb = __ldg(lg_b + d);
#pragma unroll
    for (int g = 0; g < 4; g++) { a[g] = 0.f; m2[g] = mb; lg[g] = lb; }
    for (int k = 0; k < EMB; k++) {
        float wv_ = g_wvt[(size_t)k * DK + d];
        float ml_ = g_mlt[(size_t)k * DK + d];
        float lg_ = g_lgt[(size_t)k * DK + d];
#pragma unroll
        for (int g = 0; g < 4; g++) {
            a[g]  = fmaf(wv_, ws[g][k],  a[g]);
            m2[g] = fmaf(ml_, mfs[g][k], m2[g]);
            lg[g] = fmaf(lg_, mns[g][k], lg[g]);
        }
    }
#pragma unroll
    for (int g = 0; g < 4; g++)
        feat[g][d] = fmaxf(a[g], 0.f) + fmaxf(m2[g], 0.f) + fmaxf(lg[g], 0.f);
    __syncthreads();
    float part[4] = {0.f, 0.f, 0.f, 0.f};
#pragma unroll
    for (int rep = 0; rep < 2; rep++) {
        int o = tid + rep * 256;
        float t[4];
        float pb = __ldg(ph1_b + o);
#pragma unroll
        for (int g = 0; g < 4; g++) t[g] = pb;
        for (int k = 0; k < DK; k++) {
            float w = g_ph1t[(size_t)k * 512 + o];
#pragma unroll
            for (int g = 0; g < 4; g++) t[g] = fmaf(w, feat[g][k], t[g]);
        }
        float p2 = __ldg(ph2_w + o);
#pragma unroll
        for (int g = 0; g < 4; g++) {
            float x = t[g];
            float sp = (x > 20.f) ? x : log1pf(expf(x));
            part[g] = fmaf(sp, p2, part[g]);
        }
    }
    for (int g = 0; g < 4; g++) {
        red[tid] = part[g];
        __syncthreads();
        for (int s = 128; s; s >>= 1) {
            if (tid < s) red[tid] += red[tid + s];
            __syncthreads();
        }
        if (tid == 0) out[b0 + g] = red[0] + __ldg(ph2_b);
        __syncthreads();
    }
}

// ---------------- launch ----------------
extern "C" void kernel_launch(void* const* d_in, const int* in_sizes, int n_in,
                              void* d_out, int out_size)
{
    const int*   x_type     = (const int*)d_in[0];
    const float* x_feat     = (const float*)d_in[1];
    const int*   edge_index = (const int*)d_in[2];
    const float* edge_attr  = (const float*)d_in[3];
    const int*   metal_type = (const int*)d_in[4];
    const float* metal_feat = (const float*)d_in[5];
    const float* x_emb      = (const float*)d_in[6];
    const float* x_weight   = (const float*)d_in[7];
    const float* ew1        = (const float*)d_in[8];
    const float* mlp_w      = (const float*)d_in[9];
    const float* mlp_b      = (const float*)d_in[10];
    const float* bn_g       = (const float*)d_in[11];
    const float* bn_b       = (const float*)d_in[12];
    const float* bn_rm      = (const float*)d_in[13];
    const float* bn_rv      = (const float*)d_in[14];
    const float* me1_w      = (const float*)d_in[15];
    const float* me1_b      = (const float*)d_in[16];
    const float* me2        = (const float*)d_in[17];
    const float* wq         = (const float*)d_in[18];
    const float* wk         = (const float*)d_in[19];
    const float* wv         = (const float*)d_in[20];
    const float* ml_w       = (const float*)d_in[21];
    const float* ml_b       = (const float*)d_in[22];
    const float* lg_w       = (const float*)d_in[23];
    const float* lg_b       = (const float*)d_in[24];
    const float* ph1_w      = (const float*)d_in[25];
    const float* ph1_b      = (const float*)d_in[26];
    const float* ph2_w      = (const float*)d_in[27];
    const float* ph2_b      = (const float*)d_in[28];
    float* out = (float*)d_out;

    cudaFuncSetAttribute(k_gemm_mma, cudaFuncAttributeMaxDynamicSharedMemorySize, GEMM_SMEM);

    k_init<<<(NNODES * EMB4 + 255) / 256, 256>>>(x_type, x_feat, x_emb, x_weight);
    k_wsplit<<<(NLAYERS * KPAD * KPAD + 255) / 256, 256>>>(mlp_w);
    k_mf<<<(BGR * EMB + 255) / 256, 256>>>(metal_type, metal_feat, me1_w, me1_b, me2);
    k_transpose_all<<<(4 * DK * EMB + 512 * DK + 255) / 256, 256>>>(wq, wv, ml_w, lg_w, ph1_w);
    k_ve_all<<<(NLAYERS * 2 * EMB * 32 + 255) / 256, 256>>>(ew1, mlp_w);

    // CSR build (once per launch)
    k_deg_init<<<(NNODES + 255) / 256, 256>>>();
    k_deg_count<<<(NEDGES + 255) / 256, 256>>>(edge_index);
    k_scan<<<1, 1024>>>();
    k_fill<<<(TOTE + 255) / 256, 256>>>(edge_index, edge_attr);

    dim3 gg((NPADM + 127) / 128, 2);
    for (int l = 0; l < NLAYERS; l++) {
        k_gemm_mma<<<gg, 256, GEMM_SMEM>>>(l, mlp_b + (size_t)l * EMB);
        k_aggr<<<(NNODES * 32 + 255) / 256, 256>>>(
            l,
            bn_rm + (size_t)l * EMB, bn_rv + (size_t)l * EMB,
            bn_g + (size_t)l * EMB, bn_b + (size_t)l * EMB,
            l < NLAYERS - 1 ? 1 : 0);
    }

    k_q<<<BGR / 4, 256>>>();
    k_qk<<<BGR / 4, 320>>>(wk);
    k_attn<<<BGR, 256>>>();
    k_final<<<BGR / 4, 256>>>(ml_b, lg_b, ph1_b, ph2_w, ph2_b, out);
}

// round 6
// speedup vs baseline: 1.7087x; 1.0875x over previous
#include <cuda_runtime.h>
#include <cuda_bf16.h>
#include <math.h>
#include <stdint.h>

#define NNODES 50000
#define NPADM  50048
#define NEDGES 200000
#define TOTE   (NEDGES + NNODES)
#define EMB    300
#define EMB4   75
#define KPAD   320
#define DK     256
#define BGR    1000
#define NPER   50
#define NLAYERS 5
#define PADF   16

// ---------------- scratch (device globals) ----------------
__device__ float g_h[NNODES * EMB];
__device__ float g_hW[NNODES * EMB];
__device__ __nv_bfloat16 g_hs_hi[NPADM * KPAD];
__device__ __nv_bfloat16 g_hs_lo[NPADM * KPAD];
__device__ __nv_bfloat16 g_ws_hi[NLAYERS * KPAD * KPAD];
__device__ __nv_bfloat16 g_ws_lo[NLAYERS * KPAD * KPAD];
__device__ float g_mf[BGR * EMB];
__device__ float g_ve_all[NLAYERS * 2 * EMB];
__device__ float g_Q[BGR * DK];
__device__ float g_qk[BGR * EMB];
__device__ float g_wsum[BGR * EMB];
__device__ float g_mean[BGR * EMB];
__device__ float g_wqt[EMB * DK];
__device__ float g_wvt[EMB * DK];
__device__ float g_mlt[EMB * DK];
__device__ float g_lgt[EMB * DK];
__device__ float g_ph1t[DK * 512];
// CSR
__device__ int g_deg[NNODES];
__device__ int g_off[NNODES + 1];
__device__ int g_cur[NNODES];
__device__ int g_csr_src[TOTE];
__device__ float2 g_csr_ea[TOTE];

// ---------------- helpers ----------------
__device__ __forceinline__ void store_split4(__nv_bfloat16* hh, __nv_bfloat16* hl, float4 v)
{
    float a[4] = {v.x, v.y, v.z, v.w};
    __nv_bfloat16 h[4], l[4];
#pragma unroll
    for (int q = 0; q < 4; q++) {
        h[q] = __float2bfloat16(a[q]);
        l[q] = __float2bfloat16(a[q] - __bfloat162float(h[q]));
    }
    *(__nv_bfloat162*)(hh)     = __halves2bfloat162(h[0], h[1]);
    *(__nv_bfloat162*)(hh + 2) = __halves2bfloat162(h[2], h[3]);
    *(__nv_bfloat162*)(hl)     = __halves2bfloat162(l[0], l[1]);
    *(__nv_bfloat162*)(hl + 2) = __halves2bfloat162(l[2], l[3]);
}

__device__ __forceinline__ uint32_t smem_u32(const void* p) {
    uint32_t a;
    asm("{ .reg .u64 t; cvta.to.shared.u64 t, %1; cvt.u32.u64 %0, t; }" : "=r"(a) : "l"(p));
    return a;
}

#define MMA_BF16(d, a, b) asm volatile( \
    "mma.sync.aligned.m16n8k16.row.col.f32.bf16.bf16.f32 " \
    "{%0,%1,%2,%3},{%4,%5,%6,%7},{%8,%9},{%0,%1,%2,%3};\n" \
    : "+f"(d[0]), "+f"(d[1]), "+f"(d[2]), "+f"(d[3]) \
    : "r"(a[0]), "r"(a[1]), "r"(a[2]), "r"(a[3]), "r"(b[0]), "r"(b[1]))

#define LDM4(r, a) asm volatile( \
    "ldmatrix.sync.aligned.m8n8.x4.shared.b16 {%0,%1,%2,%3}, [%4];" \
    : "=r"((r)[0]), "=r"((r)[1]), "=r"((r)[2]), "=r"((r)[3]) : "r"(a))
#define LDM2(r, a) asm volatile( \
    "ldmatrix.sync.aligned.m8n8.x2.shared.b16 {%0,%1}, [%2];" \
    : "=r"((r)[0]), "=r"((r)[1]) : "r"(a))
#define CPA16(dst, src) asm volatile( \
    "cp.async.cg.shared.global [%0], [%1], 16;" :: "r"(dst), "l"(src) : "memory")

// ---------------- node init (+ bf16 split write) ----------------
__global__ void k_init(const int* __restrict__ x_type, const float* __restrict__ x_feat,
                       const float* __restrict__ x_emb, const float* __restrict__ x_weight)
{
    int idx = blockIdx.x * blockDim.x + threadIdx.x;
    if (idx >= NNODES * EMB4) return;
    int n = idx / EMB4, c = idx % EMB4;
    int t = __ldg(x_type + n);
    float4 acc = __ldg((const float4*)(x_emb + (size_t)t * EMB) + c);
#pragma unroll
    for (int k = 0; k < PADF; k++) {
        float f = __ldg(x_feat + (size_t)n * PADF + k);
        float4 w = __ldg((const float4*)(x_weight + (size_t)k * EMB) + c);
        acc.x = fmaf(f, w.x, acc.x); acc.y = fmaf(f, w.y, acc.y);
        acc.z = fmaf(f, w.z, acc.z); acc.w = fmaf(f, w.w, acc.w);
    }
    ((float4*)g_h)[idx] = acc;
    store_split4(g_hs_hi + (size_t)n * KPAD + c * 4, g_hs_lo + (size_t)n * KPAD + c * 4, acc);
    if (c == 74) {
        __nv_bfloat162 z = __floats2bfloat162_rn(0.f, 0.f);
#pragma unroll
        for (int q = 0; q < 10; q++) {
            ((__nv_bfloat162*)(g_hs_hi + (size_t)n * KPAD + 300))[q] = z;
            ((__nv_bfloat162*)(g_hs_lo + (size_t)n * KPAD + 300))[q] = z;
        }
    }
}

// ---------------- weight split (all layers, once) ----------------
__global__ void k_wsplit(const float* __restrict__ mlp_w)
{
    int idx = blockIdx.x * blockDim.x + threadIdx.x;
    if (idx >= NLAYERS * KPAD * KPAD) return;
    int l = idx / (KPAD * KPAD), rem = idx % (KPAD * KPAD);
    int j = rem / KPAD, k = rem % KPAD;
    float v = (j < EMB && k < EMB) ? __ldg(mlp_w + (size_t)l * EMB * EMB + (size_t)j * EMB + k) : 0.f;
    __nv_bfloat16 hi = __float2bfloat16(v);
    g_ws_hi[idx] = hi;
    g_ws_lo[idx] = __float2bfloat16(v - __bfloat162float(hi));
}

// ---------------- metal feature ----------------
__global__ void k_mf(const int* __restrict__ metal_type, const float* __restrict__ metal_feat,
                     const float* __restrict__ me1_w, const float* __restrict__ me1_b,
                     const float* __restrict__ me2)
{
    int idx = blockIdx.x * blockDim.x + threadIdx.x;
    if (idx >= BGR * EMB) return;
    int b = idx / EMB, j = idx % EMB;
    float acc = __ldg(me1_b + j) + __ldg(me2 + (size_t)__ldg(metal_type + b) * EMB + j);
#pragma unroll
    for (int k = 0; k < 17; k++)
        acc = fmaf(__ldg(metal_feat + (size_t)b * 17 + k), __ldg(me1_w + (size_t)j * 17 + k), acc);
    g_mf[idx] = acc;
}

// ---------------- transpose readout weights ----------------
__global__ void k_transpose_all(const float* __restrict__ wq, const float* __restrict__ wv,
                                const float* __restrict__ ml, const float* __restrict__ lg,
                                const float* __restrict__ ph1)
{
    int idx = blockIdx.x * blockDim.x + threadIdx.x;
    const int SZ1 = DK * EMB;
    if (idx < 4 * SZ1) {
        int w = idx / SZ1, i = idx % SZ1;
        int d = i / EMB, j = i % EMB;
        float v = (w == 0) ? wq[i] : (w == 1) ? wv[i] : (w == 2) ? ml[i] : lg[i];
        float* dst = (w == 0) ? g_wqt : (w == 1) ? g_wvt : (w == 2) ? g_mlt : g_lgt;
        dst[(size_t)j * DK + d] = v;
    } else {
        int i = idx - 4 * SZ1;
        if (i < 512 * DK) {
            int o = i / DK, d = i % DK;
            g_ph1t[(size_t)d * 512 + o] = ph1[i];
        }
    }
}

// ---------------- all layers' edge vectors ----------------
__global__ void k_ve_all(const float* __restrict__ ew1, const float* __restrict__ mlp_w)
{
    int o = (blockIdx.x * blockDim.x + threadIdx.x) >> 5;
    if (o >= NLAYERS * 2 * EMB) return;
    int lane = threadIdx.x & 31;
    int l = o / (2 * EMB);
    int rem = o % (2 * EMB);
    int w = rem / EMB, col = rem % EMB;
    const float* e = ew1 + (size_t)l * 2 * EMB + (size_t)w * EMB;
    const float* wr = mlp_w + (size_t)l * EMB * EMB + (size_t)col * EMB;
    float s = 0.f;
    for (int k = lane; k < EMB; k += 32) s = fmaf(__ldg(e + k), __ldg(wr + k), s);
#pragma unroll
    for (int off = 16; off; off >>= 1) s += __shfl_xor_sync(0xffffffffu, s, off);
    if (lane == 0) g_ve_all[o] = s;
}

// ---------------- CSR build ----------------
__global__ void k_deg_init() {
    int i = blockIdx.x * blockDim.x + threadIdx.x;
    if (i < NNODES) g_deg[i] = 1;
}
__global__ void k_deg_count(const int* __restrict__ eidx) {
    int e = blockIdx.x * blockDim.x + threadIdx.x;
    if (e < NEDGES) atomicAdd(&g_deg[__ldg(eidx + NEDGES + e)], 1);
}
__global__ void k_scan() {
    __shared__ int ps[1024];
    const int C = (NNODES + 1023) / 1024;
    int t = threadIdx.x;
    int base = t * C;
    int s = 0;
    for (int i = base; i < base + C && i < NNODES; i++) s += g_deg[i];
    ps[t] = s;
    __syncthreads();
    for (int off = 1; off < 1024; off <<= 1) {
        int v = (t >= off) ? ps[t - off] : 0;
        __syncthreads();
        ps[t] += v;
        __syncthreads();
    }
    int ex = (t == 0) ? 0 : ps[t - 1];
    for (int i = base; i < base + C && i < NNODES; i++) {
        g_off[i] = ex; g_cur[i] = ex;
        ex += g_deg[i];
    }
    if (t == 1023) g_off[NNODES] = TOTE;
}
__global__ void k_fill(const int* __restrict__ eidx, const float* __restrict__ eattr) {
    int idx = blockIdx.x * blockDim.x + threadIdx.x;
    if (idx >= TOTE) return;
    int src, col; float2 ea;
    if (idx < NEDGES) {
        src = __ldg(eidx + idx);
        col = __ldg(eidx + NEDGES + idx);
        ea = __ldg((const float2*)eattr + idx);
    } else {
        src = col = idx - NEDGES;
        ea = make_float2(0.f, 4.f);
    }
    int pos = atomicAdd(&g_cur[col], 1);
    g_csr_src[pos] = src;
    g_csr_ea[pos] = ea;
}

// ---------------- GEMM: hW = h @ W.T + b  (bf16 3-split, 128x112 tile, 2 CTA/SM) --
// K chunks of 32, double-buffered cp.async. Row stride 80B (32 bf16 + 8 pad).
// Stage layout: A_hi@0 (128x80=10240), A_lo@10240, B_hi@20480 (112x80=8960),
// B_lo@29440; stage = 38400, double = 76800.
#define ROWB   80
#define OA_LO  10240
#define OB_HI  20480
#define OB_LO  29440
#define STG_SZ 38400
#define GEMM_SMEM (2 * STG_SZ)

__device__ __forceinline__ void gemm_prefetch(uint32_t sbase, int layer, int m0, int j0,
                                              int k0, int tid)
{
    // A: 1024 16B ops (hi 512 + lo 512)
#pragma unroll
    for (int it = 0; it < 4; it++) {
        int f = tid + it * 256;
        int sel = f >> 9, e = f & 511;
        int r = e >> 2, c4 = e & 3;
        uint32_t dst = sbase + (sel ? OA_LO : 0) + r * ROWB + c4 * 16;
        const __nv_bfloat16* src = (sel ? g_hs_lo : g_hs_hi) + (size_t)(m0 + r) * KPAD + k0 + c4 * 8;
        CPA16(dst, src);
    }
    // B: 896 16B ops (hi 448 + lo 448), rows clamped to KPAD
#pragma unroll
    for (int it = 0; it < 4; it++) {
        int f = tid + it * 256;
        if (f < 896) {
            int sel = (f >= 448) ? 1 : 0;
            int e = sel ? f - 448 : f;
            int r = e >> 2, c4 = e & 3;
            int j = j0 + r;
            int jr = (j < KPAD) ? j : 0;
            uint32_t dst = sbase + (sel ? OB_LO : OB_HI) + r * ROWB + c4 * 16;
            const __nv_bfloat16* src = (sel ? g_ws_lo : g_ws_hi)
                                       + ((size_t)layer * KPAD + jr) * KPAD + k0 + c4 * 8;
            CPA16(dst, src);
        }
    }
    asm volatile("cp.async.commit_group;" ::: "memory");
}

__global__ void __launch_bounds__(256, 2) k_gemm_mma(int layer, const float* __restrict__ bias)
{
    extern __shared__ char smem[];
    uint32_t sb = smem_u32(smem);
    int tid = threadIdx.x, warp = tid >> 5, lane = tid & 31;
    int gid = lane >> 2, tig = lane & 3;
    int wm = warp & 3, wn = warp >> 2;       // 4 (M) x 2 (N) warps
    int m0 = blockIdx.x * 128, j0 = blockIdx.y * 112;

    float acc[2][7][4];
#pragma unroll
    for (int mt = 0; mt < 2; mt++)
#pragma unroll
        for (int nj = 0; nj < 7; nj++)
#pragma unroll
            for (int r = 0; r < 4; r++) acc[mt][nj][r] = 0.f;

    int arowB = (wm * 32 + (lane & 15)) * ROWB + 16 * (lane >> 4);
    int nb = wn * 56;
    int brow4B = (nb + 8 * (lane >> 4) + (lane & 7)) * ROWB + 16 * ((lane >> 3) & 1);
    int brow2B = (nb + 48 + (lane & 7)) * ROWB + 16 * ((lane >> 3) & 1);

    gemm_prefetch(sb, layer, m0, j0, 0, tid);

    for (int kc = 0; kc < 10; kc++) {
        int cur = kc & 1;
        asm volatile("cp.async.wait_group 0;" ::: "memory");
        __syncthreads();
        if (kc < 9)
            gemm_prefetch(sb + (1 - cur) * STG_SZ, layer, m0, j0, (kc + 1) * 32, tid);

        uint32_t Ab = sb + cur * STG_SZ;
#pragma unroll
        for (int ks = 0; ks < 2; ks++) {
            int kbB = ks * 32;
            uint32_t ah[2][4], al[2][4], bh[7][2], bl[7][2];
#pragma unroll
            for (int mt = 0; mt < 2; mt++)
                LDM4(ah[mt], Ab + arowB + mt * (16 * ROWB) + kbB);
#pragma unroll
            for (int pr = 0; pr < 3; pr++) {
                uint32_t t[4];
                LDM4(t, Ab + OB_HI + brow4B + pr * (16 * ROWB) + kbB);
                bh[2 * pr][0] = t[0]; bh[2 * pr][1] = t[1];
                bh[2 * pr + 1][0] = t[2]; bh[2 * pr + 1][1] = t[3];
            }
            LDM2(bh[6], Ab + OB_HI + brow2B + kbB);
            // pass 1: hi x hi
#pragma unroll
            for (int mt = 0; mt < 2; mt++)
#pragma unroll
                for (int nj = 0; nj < 7; nj++) MMA_BF16(acc[mt][nj], ah[mt], bh[nj]);
            // pass 2: lo x hi
#pragma unroll
            for (int mt = 0; mt < 2; mt++)
                LDM4(al[mt], Ab + OA_LO + arowB + mt * (16 * ROWB) + kbB);
#pragma unroll
            for (int mt = 0; mt < 2; mt++)
#pragma unroll
                for (int nj = 0; nj < 7; nj++) MMA_BF16(acc[mt][nj], al[mt], bh[nj]);
            // pass 3: hi x lo
#pragma unroll
            for (int pr = 0; pr < 3; pr++) {
                uint32_t t[4];
                LDM4(t, Ab + OB_LO + brow4B + pr * (16 * ROWB) + kbB);
                bl[2 * pr][0] = t[0]; bl[2 * pr][1] = t[1];
                bl[2 * pr + 1][0] = t[2]; bl[2 * pr + 1][1] = t[3];
            }
            LDM2(bl[6], Ab + OB_LO + brow2B + kbB);
#pragma unroll
            for (int mt = 0; mt < 2; mt++)
#pragma unroll
                for (int nj = 0; nj < 7; nj++) MMA_BF16(acc[mt][nj], ah[mt], bl[nj]);
        }
        __syncthreads();
    }

    // epilogue: + bias, store fp32
#pragma unroll
    for (int mt = 0; mt < 2; mt++) {
        int m = m0 + wm * 32 + mt * 16 + gid;
#pragma unroll
        for (int nj = 0; nj < 7; nj++) {
            int j = j0 + nb + nj * 8 + 2 * tig;
            if (j < EMB) {
                float b0 = __ldg(bias + j), b1 = __ldg(bias + j + 1);
                if (m < NNODES)
                    *(float2*)(g_hW + (size_t)m * EMB + j) =
                        make_float2(acc[mt][nj][0] + b0, acc[mt][nj][1] + b1);
                if (m + 8 < NNODES)
                    *(float2*)(g_hW + (size_t)(m + 8) * EMB + j) =
                        make_float2(acc[mt][nj][2] + b0, acc[mt][nj][3] + b1);
            }
        }
    }
}

// ---------------- pull aggregation + BN (+relu), fused; conditional stores -------
__global__ void __launch_bounds__(256) k_aggr(int layer,
                                              const float* __restrict__ rm,
                                              const float* __restrict__ rv,
                                              const float* __restrict__ gg,
                                              const float* __restrict__ bb,
                                              int do_relu, int store_h, int store_split)
{
    int gw = (blockIdx.x * blockDim.x + threadIdx.x) >> 5;
    if (gw >= NNODES) return;
    int lane = threadIdx.x & 31;
    const float4* ve4 = (const float4*)(g_ve_all + (size_t)layer * 2 * EMB);

    float4 acc[3], e0[3], e1[3];
#pragma unroll
    for (int i = 0; i < 3; i++) {
        acc[i] = make_float4(0.f, 0.f, 0.f, 0.f);
        int c = lane + 32 * i;
        if (c < EMB4) { e0[i] = __ldg(ve4 + c); e1[i] = __ldg(ve4 + EMB4 + c); }
    }
    int beg = g_off[gw], end = g_off[gw + 1];
    for (int e = beg; e < end; e++) {
        int src = g_csr_src[e];
        float2 ea = g_csr_ea[e];
        const float4* row = (const float4*)(g_hW + (size_t)src * EMB);
#pragma unroll
        for (int i = 0; i < 3; i++) {
            int c = lane + 32 * i;
            if (c < EMB4) {
                float4 x = row[c];
                acc[i].x += fmaxf(fmaf(ea.y, e1[i].x, fmaf(ea.x, e0[i].x, x.x)), 0.f);
                acc[i].y += fmaxf(fmaf(ea.y, e1[i].y, fmaf(ea.x, e0[i].y, x.y)), 0.f);
                acc[i].z += fmaxf(fmaf(ea.y, e1[i].z, fmaf(ea.x, e0[i].z, x.z)), 0.f);
                acc[i].w += fmaxf(fmaf(ea.y, e1[i].w, fmaf(ea.x, e0[i].w, x.w)), 0.f);
            }
        }
    }
#pragma unroll
    for (int i = 0; i < 3; i++) {
        int c = lane + 32 * i;
        if (c < EMB4) {
            float4 m = __ldg((const float4*)rm + c);
            float4 v = __ldg((const float4*)rv + c);
            float4 g4 = __ldg((const float4*)gg + c);
            float4 b4 = __ldg((const float4*)bb + c);
            float4 y;
            y.x = (acc[i].x - m.x) * rsqrtf(v.x + 1e-5f) * g4.x + b4.x;
            y.y = (acc[i].y - m.y) * rsqrtf(v.y + 1e-5f) * g4.y + b4.y;
            y.z = (acc[i].z - m.z) * rsqrtf(v.z + 1e-5f) * g4.z + b4.z;
            y.w = (acc[i].w - m.w) * rsqrtf(v.w + 1e-5f) * g4.w + b4.w;
            if (do_relu) {
                y.x = fmaxf(y.x, 0.f); y.y = fmaxf(y.y, 0.f);
                y.z = fmaxf(y.z, 0.f); y.w = fmaxf(y.w, 0.f);
            }
            if (store_h) ((float4*)(g_h + (size_t)gw * EMB))[c] = y;
            if (store_split)
                store_split4(g_hs_hi + (size_t)gw * KPAD + c * 4,
                             g_hs_lo + (size_t)gw * KPAD + c * 4, y);
        }
    }
}

// ---------------- readout ----------------
__global__ void k_q()
{
    __shared__ float mfs[4][EMB];
    int b0 = blockIdx.x * 4, tid = threadIdx.x;
    for (int i = tid; i < 4 * EMB; i += 256)
        mfs[i / EMB][i % EMB] = g_mf[(size_t)(b0 + i / EMB) * EMB + i % EMB];
    __syncthreads();
    float acc[4] = {0.f, 0.f, 0.f, 0.f};
    for (int j = 0; j < EMB; j++) {
        float w = g_wqt[(size_t)j * DK + tid];
#pragma unroll
        for (int g = 0; g < 4; g++) acc[g] = fmaf(mfs[g][j], w, acc[g]);
    }
#pragma unroll
    for (int g = 0; g < 4; g++) g_Q[(size_t)(b0 + g) * DK + tid] = acc[g];
}

__global__ void k_qk(const float* __restrict__ wk)
{
    __shared__ float Qs[4][DK];
    int b0 = blockIdx.x * 4, tid = threadIdx.x;
    for (int i = tid; i < 4 * DK; i += 320)
        Qs[i / DK][i % DK] = g_Q[(size_t)(b0 + i / DK) * DK + i % DK];
    __syncthreads();
    if (tid < EMB) {
        float acc[4] = {0.f, 0.f, 0.f, 0.f};
        for (int d = 0; d < DK; d++) {
            float w = __ldg(wk + (size_t)d * EMB + tid);
#pragma unroll
            for (int g = 0; g < 4; g++) acc[g] = fmaf(Qs[g][d], w, acc[g]);
        }
#pragma unroll
        for (int g = 0; g < 4; g++) g_qk[(size_t)(b0 + g) * EMB + tid] = acc[g];
    }
}

__global__ void k_attn()
{
    __shared__ float qks[EMB];
    __shared__ float sc[NPER];
    __shared__ float p[NPER];
    int b = blockIdx.x, tid = threadIdx.x;
    for (int i = tid; i < EMB; i += 256) qks[i] = g_qk[(size_t)b * EMB + i];
    __syncthreads();
    int warp = tid >> 5, lane = tid & 31;
    const float* hb = g_h + (size_t)b * NPER * EMB;
    for (int k = warp; k < NPER; k += 8) {
        float s = 0.f;
        for (int i = lane; i < EMB; i += 32) s = fmaf(qks[i], hb[(size_t)k * EMB + i], s);
#pragma unroll
        for (int off = 16; off; off >>= 1) s += __shfl_xor_sync(0xffffffffu, s, off);
        if (lane == 0) sc[k] = s * (1.0f / 16.0f);
    }
    __syncthreads();
    if (tid == 0) {
        float mx = -1e30f;
        for (int k = 0; k < NPER; k++) mx = fmaxf(mx, sc[k]);
        float ssum = 0.f;
        for (int k = 0; k < NPER; k++) { float e = expf(sc[k] - mx); p[k] = e; ssum += e; }
        float inv = 1.f / ssum;
        for (int k = 0; k < NPER; k++) p[k] *= inv;
    }
    __syncthreads();
    for (int j = tid; j < EMB; j += 256) {
        float ws = 0.f, mn = 0.f;
        for (int k = 0; k < NPER; k++) {
            float v = hb[(size_t)k * EMB + j];
            ws = fmaf(p[k], v, ws); mn += v;
        }
        g_wsum[(size_t)b * EMB + j] = ws;
        g_mean[(size_t)b * EMB + j] = mn * (1.0f / NPER);
    }
}

__global__ void k_final(const float* __restrict__ ml_b, const float* __restrict__ lg_b,
                        const float* __restrict__ ph1_b, const float* __restrict__ ph2_w,
                        const float* __restrict__ ph2_b, float* __restrict__ out)
{
    __shared__ float ws[4][EMB], mfs[4][EMB], mns[4][EMB];
    __shared__ float feat[4][DK];
    __shared__ float red[256];
    int b0 = blockIdx.x * 4, tid = threadIdx.x;
    for (int i = tid; i < 4 * EMB; i += 256) {
        int g = i / EMB, j = i % EMB;
        ws[g][j]  = g_wsum[(size_t)(b0 + g) * EMB + j];
        mfs[g][j] = g_mf[(size_t)(b0 + g) * EMB + j];
        mns[g][j] = g_mean[(size_t)(b0 + g) * EMB + j];
    }
    __syncthreads();
    int d = tid;
    float a[4], m2[4], lg[4];
    float mb = __ldg(ml_b + d), lb = __ldg(lg_b + d);
#pragma unroll
    for (int g = 0; g < 4; g++) { a[g] = 0.f; m2[g] = mb; lg[g] = lb; }
    for (int k = 0; k < EMB; k++) {
        float wv_ = g_wvt[(size_t)k * DK + d];
        float ml_ = g_mlt[(size_t)k * DK + d];
        float lg_ = g_lgt[(size_t)k * DK + d];
#pragma unroll
        for (int g = 0; g < 4; g++) {
            a[g]  = fmaf(wv_, ws[g][k],  a[g]);
            m2[g] = fmaf(ml_, mfs[g][k], m2[g]);
            lg[g] = fmaf(lg_, mns[g][k], lg[g]);
        }
    }
#pragma unroll
    for (int g = 0; g < 4; g++)
        feat[g][d] = fmaxf(a[g], 0.f) + fmaxf(m2[g], 0.f) + fmaxf(lg[g], 0.f);
    __syncthreads();
    float part[4] = {0.f, 0.f, 0.f, 0.f};
#pragma unroll
    for (int rep = 0; rep < 2; rep++) {
        int o = tid + rep * 256;
        float t[4];
        float pb = __ldg(ph1_b + o);
#pragma unroll
        for (int g = 0; g < 4; g++) t[g] = pb;
        for (int k = 0; k < DK; k++) {
            float w = g_ph1t[(size_t)k * 512 + o];
#pragma unroll
            for (int g = 0; g < 4; g++) t[g] = fmaf(w, feat[g][k], t[g]);
        }
        float p2 = __ldg(ph2_w + o);
#pragma unroll
        for (int g = 0; g < 4; g++) {
            float x = t[g];
            float sp = (x > 20.f) ? x : log1pf(expf(x));
            part[g] = fmaf(sp, p2, part[g]);
        }
    }
    for (int g = 0; g < 4; g++) {
        red[tid] = part[g];
        __syncthreads();
        for (int s = 128; s; s >>= 1) {
            if (tid < s) red[tid] += red[tid + s];
            __syncthreads();
        }
        if (tid == 0) out[b0 + g] = red[0] + __ldg(ph2_b);
        __syncthreads();
    }
}

// ---------------- launch ----------------
extern "C" void kernel_launch(void* const* d_in, const int* in_sizes, int n_in,
                              void* d_out, int out_size)
{
    const int*   x_type     = (const int*)d_in[0];
    const float* x_feat     = (const float*)d_in[1];
    const int*   edge_index = (const int*)d_in[2];
    const float* edge_attr  = (const float*)d_in[3];
    const int*   metal_type = (const int*)d_in[4];
    const float* metal_feat = (const float*)d_in[5];
    const float* x_emb      = (const float*)d_in[6];
    const float* x_weight   = (const float*)d_in[7];
    const float* ew1        = (const float*)d_in[8];
    const float* mlp_w      = (const float*)d_in[9];
    const float* mlp_b      = (const float*)d_in[10];
    const float* bn_g       = (const float*)d_in[11];
    const float* bn_b       = (const float*)d_in[12];
    const float* bn_rm      = (const float*)d_in[13];
    const float* bn_rv      = (const float*)d_in[14];
    const float* me1_w      = (const float*)d_in[15];
    const float* me1_b      = (const float*)d_in[16];
    const float* me2        = (const float*)d_in[17];
    const float* wq         = (const float*)d_in[18];
    const float* wk         = (const float*)d_in[19];
    const float* wv         = (const float*)d_in[20];
    const float* ml_w       = (const float*)d_in[21];
    const float* ml_b       = (const float*)d_in[22];
    const float* lg_w       = (const float*)d_in[23];
    const float* lg_b       = (const float*)d_in[24];
    const float* ph1_w      = (const float*)d_in[25];
    const float* ph1_b      = (const float*)d_in[26];
    const float* ph2_w      = (const float*)d_in[27];
    const float* ph2_b      = (const float*)d_in[28];
    float* out = (float*)d_out;

    cudaFuncSetAttribute(k_gemm_mma, cudaFuncAttributeMaxDynamicSharedMemorySize, GEMM_SMEM);

    k_init<<<(NNODES * EMB4 + 255) / 256, 256>>>(x_type, x_feat, x_emb, x_weight);
    k_wsplit<<<(NLAYERS * KPAD * KPAD + 255) / 256, 256>>>(mlp_w);
    k_mf<<<(BGR * EMB + 255) / 256, 256>>>(metal_type, metal_feat, me1_w, me1_b, me2);
    k_transpose_all<<<(4 * DK * EMB + 512 * DK + 255) / 256, 256>>>(wq, wv, ml_w, lg_w, ph1_w);
    k_ve_all<<<(NLAYERS * 2 * EMB * 32 + 255) / 256, 256>>>(ew1, mlp_w);

    // CSR build (once per launch)
    k_deg_init<<<(NNODES + 255) / 256, 256>>>();
    k_deg_count<<<(NEDGES + 255) / 256, 256>>>(edge_index);
    k_scan<<<1, 1024>>>();
    k_fill<<<(TOTE + 255) / 256, 256>>>(edge_index, edge_attr);

    dim3 gg(NPADM / 128, 3);
    for (int l = 0; l < NLAYERS; l++) {
        int last = (l == NLAYERS - 1);
        k_gemm_mma<<<gg, 256, GEMM_SMEM>>>(l, mlp_b + (size_t)l * EMB);
        k_aggr<<<(NNODES * 32 + 255) / 256, 256>>>(
            l,
            bn_rm + (size_t)l * EMB, bn_rv + (size_t)l * EMB,
            bn_g + (size_t)l * EMB, bn_b + (size_t)l * EMB,
            last ? 0 : 1, last ? 1 : 0, last ? 0 : 1);
    }

    k_q<<<BGR / 4, 256>>>();
    k_qk<<<BGR / 4, 320>>>(wk);
    k_attn<<<BGR, 256>>>();
    k_final<<<BGR / 4, 256>>>(ml_b, lg_b, ph1_b, ph2_w, ph2_b, out);
}